// round 1
// baseline (speedup 1.0000x reference)
#include <cuda_runtime.h>
#include <cuda_bf16.h>
#include <math.h>

// ---------------- problem constants ----------------
#define B_SZ     2
#define S_LEN    2048
#define D_MODEL  1024
#define NUM_H    16
#define HEAD_D   64
#define FF_DIM   4096
#define N_TOK    (B_SZ * S_LEN)        // 4096
#define MAXM1    4999                  // MAX_SEQ_LEN - 1

// ---------------- scratch (static device globals; no allocation) ----------------
__device__ float g_xn [N_TOK * D_MODEL];
__device__ float g_q  [N_TOK * D_MODEL];
__device__ float g_k  [N_TOK * D_MODEL];
__device__ float g_v  [N_TOK * D_MODEL];
__device__ float g_ctx[N_TOK * D_MODEL];
__device__ float g_x1 [N_TOK * D_MODEL];
__device__ float g_h  [N_TOK * FF_DIM];

// ---------------- LayerNorm: one block per row ----------------
__global__ __launch_bounds__(256) void ln_kernel(
    const float* __restrict__ x, const float* __restrict__ gamma,
    const float* __restrict__ beta, float* __restrict__ out)
{
    int row = blockIdx.x;
    int tid = threadIdx.x;
    const float4* xr = (const float4*)(x + (size_t)row * D_MODEL);
    float4 v = xr[tid];
    float s  = v.x + v.y + v.z + v.w;
    float ss = v.x*v.x + v.y*v.y + v.z*v.z + v.w*v.w;
    #pragma unroll
    for (int o = 16; o; o >>= 1) {
        s  += __shfl_xor_sync(0xffffffffu, s,  o);
        ss += __shfl_xor_sync(0xffffffffu, ss, o);
    }
    __shared__ float rs[8], rss[8];
    int w = tid >> 5;
    if ((tid & 31) == 0) { rs[w] = s; rss[w] = ss; }
    __syncthreads();
    float S0 = 0.f, SS0 = 0.f;
    #pragma unroll
    for (int i = 0; i < 8; i++) { S0 += rs[i]; SS0 += rss[i]; }
    float mean = S0 * (1.0f / D_MODEL);
    float var  = SS0 * (1.0f / D_MODEL) - mean * mean;
    float rstd = rsqrtf(var + 1e-5f);
    float4 gg = ((const float4*)gamma)[tid];
    float4 bb = ((const float4*)beta)[tid];
    float4 o;
    o.x = (v.x - mean) * rstd * gg.x + bb.x;
    o.y = (v.y - mean) * rstd * gg.y + bb.y;
    o.z = (v.z - mean) * rstd * gg.z + bb.z;
    o.w = (v.w - mean) * rstd * gg.w + bb.w;
    ((float4*)(out + (size_t)row * D_MODEL))[tid] = o;
}

// ---------------- SGEMM: C = A(MxK) @ W(KxN) + bias  (+ epilogue) ----------------
// EPI: 0 = bias only, 1 = bias + exact GELU, 2 = bias + residual add
__device__ __forceinline__ float gelu_exact(float x) {
    return 0.5f * x * (1.0f + erff(x * 0.70710678118654752f));
}

template<int EPI>
__global__ __launch_bounds__(256) void gemm_kernel(
    const float* __restrict__ A, const float* __restrict__ W,
    const float* __restrict__ bias, const float* __restrict__ res,
    float* __restrict__ C, int M, int N, int K)
{
    __shared__ float As[16 * 128];   // [k][m]
    __shared__ float Bs[16 * 128];   // [k][n]
    int tid = threadIdx.x;
    int tx = tid & 15, ty = tid >> 4;
    int bm = blockIdx.y * 128, bn = blockIdx.x * 128;

    float acc[8][8];
    #pragma unroll
    for (int i = 0; i < 8; i++)
        #pragma unroll
        for (int j = 0; j < 8; j++) acc[i][j] = 0.f;

    for (int k0 = 0; k0 < K; k0 += 16) {
        // A tile: 128 rows x 16 k, transposed into As[k][m]
        #pragma unroll
        for (int l = 0; l < 2; l++) {
            int f = tid + l * 256;          // 0..511 float4 ids
            int row = f >> 2;               // 0..127
            int c4  = (f & 3) * 4;          // 0,4,8,12
            float4 v = *(const float4*)&A[(size_t)(bm + row) * K + k0 + c4];
            As[(c4 + 0) * 128 + row] = v.x;
            As[(c4 + 1) * 128 + row] = v.y;
            As[(c4 + 2) * 128 + row] = v.z;
            As[(c4 + 3) * 128 + row] = v.w;
        }
        // B tile: 16 rows x 128 n, natural
        #pragma unroll
        for (int l = 0; l < 2; l++) {
            int f = tid + l * 256;
            int row = f >> 5;               // 0..15
            int c4  = (f & 31) * 4;         // 0..124
            *(float4*)&Bs[row * 128 + c4] =
                *(const float4*)&W[(size_t)(k0 + row) * N + bn + c4];
        }
        __syncthreads();
        #pragma unroll
        for (int kk = 0; kk < 16; kk++) {
            float a[8], b[8];
            *(float4*)&a[0] = *(float4*)&As[kk * 128 + ty * 8];
            *(float4*)&a[4] = *(float4*)&As[kk * 128 + ty * 8 + 4];
            *(float4*)&b[0] = *(float4*)&Bs[kk * 128 + tx * 8];
            *(float4*)&b[4] = *(float4*)&Bs[kk * 128 + tx * 8 + 4];
            #pragma unroll
            for (int i = 0; i < 8; i++)
                #pragma unroll
                for (int j = 0; j < 8; j++)
                    acc[i][j] += a[i] * b[j];
        }
        __syncthreads();
    }

    float bv[8];
    #pragma unroll
    for (int j = 0; j < 8; j++) bv[j] = bias[bn + tx * 8 + j];

    #pragma unroll
    for (int i = 0; i < 8; i++) {
        size_t m = (size_t)(bm + ty * 8 + i);
        size_t base = m * N + bn + tx * 8;
        #pragma unroll
        for (int j0 = 0; j0 < 8; j0 += 4) {
            float c[4];
            #pragma unroll
            for (int j = 0; j < 4; j++) {
                float cc = acc[i][j0 + j] + bv[j0 + j];
                if (EPI == 1) cc = gelu_exact(cc);
                if (EPI == 2) cc += res[base + j0 + j];
                c[j] = cc;
            }
            *(float4*)&C[base + j0] = make_float4(c[0], c[1], c[2], c[3]);
        }
    }
}

// ---------------- Flash attention with relative position bias + mask ----------------
// grid: (S/64, H, B), block 256 (16x16), micro-tile 4q x 4{k|dv}
__global__ __launch_bounds__(256) void attn_kernel(
    const float* __restrict__ Q, const float* __restrict__ K,
    const float* __restrict__ V, const float* __restrict__ bt,
    const int* __restrict__ mask, float* __restrict__ O)
{
    __shared__ float Qt [64 * 64];   // [d][q]  (Q transposed)
    __shared__ float KPt[64 * 64];   // [d][k] during scores, [q][k] for P in PV
    __shared__ float Vs [64 * 64];   // [k][dv]

    int b  = blockIdx.z, h = blockIdx.y;
    int q0 = blockIdx.x * 64;
    int tid = threadIdx.x;
    int tx = tid & 15, ty = tid >> 4;

    const float* Qb = Q + ((size_t)b * S_LEN + q0) * D_MODEL + h * HEAD_D;
    const float* Kb = K + ((size_t)b * S_LEN) * D_MODEL + h * HEAD_D;
    const float* Vb = V + ((size_t)b * S_LEN) * D_MODEL + h * HEAD_D;

    // load Q tile transposed: 64q x 64d
    #pragma unroll
    for (int l = 0; l < 4; l++) {
        int f  = tid + l * 256;           // 0..1023 float4 ids
        int qq = f >> 4;                  // 0..63
        int d4 = (f & 15) * 4;            // 0..60
        float4 v = *(const float4*)&Qb[(size_t)qq * D_MODEL + d4];
        Qt[(d4 + 0) * 64 + qq] = v.x;
        Qt[(d4 + 1) * 64 + qq] = v.y;
        Qt[(d4 + 2) * 64 + qq] = v.z;
        Qt[(d4 + 3) * 64 + qq] = v.w;
    }

    float m_[4], l_[4], ctx[4][4];
    #pragma unroll
    for (int i = 0; i < 4; i++) {
        m_[i] = -1e30f; l_[i] = 0.f;
        #pragma unroll
        for (int j = 0; j < 4; j++) ctx[i][j] = 0.f;
    }

    for (int kt = 0; kt < S_LEN / 64; kt++) {
        int k0 = kt * 64;
        __syncthreads();   // previous PV done reading KPt/Vs
        // load K (transposed) and V (natural)
        #pragma unroll
        for (int l = 0; l < 4; l++) {
            int f  = tid + l * 256;
            int kk = f >> 4;
            int d4 = (f & 15) * 4;
            float4 kv = *(const float4*)&Kb[(size_t)(k0 + kk) * D_MODEL + d4];
            KPt[(d4 + 0) * 64 + kk] = kv.x;
            KPt[(d4 + 1) * 64 + kk] = kv.y;
            KPt[(d4 + 2) * 64 + kk] = kv.z;
            KPt[(d4 + 3) * 64 + kk] = kv.w;
            float4 vv = *(const float4*)&Vb[(size_t)(k0 + kk) * D_MODEL + d4];
            *(float4*)&Vs[kk * 64 + d4] = vv;
        }
        __syncthreads();

        // scores: sacc[q][k] = sum_d Qt[d][q] * Kt[d][k]
        float sacc[4][4];
        #pragma unroll
        for (int i = 0; i < 4; i++)
            #pragma unroll
            for (int j = 0; j < 4; j++) sacc[i][j] = 0.f;

        #pragma unroll 8
        for (int d = 0; d < 64; d++) {
            float4 av = *(float4*)&Qt [d * 64 + ty * 4];
            float4 bb = *(float4*)&KPt[d * 64 + tx * 4];
            float a[4] = {av.x, av.y, av.z, av.w};
            float bq[4] = {bb.x, bb.y, bb.z, bb.w};
            #pragma unroll
            for (int i = 0; i < 4; i++)
                #pragma unroll
                for (int j = 0; j < 4; j++)
                    sacc[i][j] += a[i] * bq[j];
        }

        // scale + rel-pos bias + mask
        #pragma unroll
        for (int i = 0; i < 4; i++) {
            int qg = q0 + ty * 4 + i;
            #pragma unroll
            for (int j = 0; j < 4; j++) {
                int kg = k0 + tx * 4 + j;
                float sc = sacc[i][j] * 0.125f
                         + bt[(size_t)(kg - qg + MAXM1) * NUM_H + h];
                int mv = mask[((size_t)b * S_LEN + qg) * S_LEN + kg];
                sacc[i][j] = mv ? sc : -1e9f;
            }
        }

        __syncthreads();   // everyone done reading KPt (K) before P overwrite

        // online softmax; P stored naturally [q][k] into KPt
        #pragma unroll
        for (int i = 0; i < 4; i++) {
            float tm = fmaxf(fmaxf(sacc[i][0], sacc[i][1]),
                             fmaxf(sacc[i][2], sacc[i][3]));
            #pragma unroll
            for (int o = 8; o; o >>= 1)
                tm = fmaxf(tm, __shfl_xor_sync(0xffffffffu, tm, o));
            float mn   = fmaxf(m_[i], tm);
            float corr = __expf(m_[i] - mn);
            float pr[4]; float rs = 0.f;
            #pragma unroll
            for (int j = 0; j < 4; j++) {
                pr[j] = __expf(sacc[i][j] - mn);
                rs += pr[j];
            }
            *(float4*)&KPt[(ty * 4 + i) * 64 + tx * 4] =
                make_float4(pr[0], pr[1], pr[2], pr[3]);
            #pragma unroll
            for (int o = 8; o; o >>= 1)
                rs += __shfl_xor_sync(0xffffffffu, rs, o);
            l_[i] = l_[i] * corr + rs;
            m_[i] = mn;
            #pragma unroll
            for (int j = 0; j < 4; j++) ctx[i][j] *= corr;
        }
        __syncthreads();

        // PV: ctx[q][dv] += P[q][k] * V[k][dv]
        #pragma unroll 8
        for (int kk = 0; kk < 64; kk++) {
            float4 vv = *(const float4*)&Vs[kk * 64 + tx * 4];
            float vj[4] = {vv.x, vv.y, vv.z, vv.w};
            #pragma unroll
            for (int i = 0; i < 4; i++) {
                float p = KPt[(ty * 4 + i) * 64 + kk];
                #pragma unroll
                for (int j = 0; j < 4; j++)
                    ctx[i][j] += p * vj[j];
            }
        }
    }

    // finalize & write ctx (b, q, h, dv) -> row-major (token, D_MODEL)
    #pragma unroll
    for (int i = 0; i < 4; i++) {
        float inv = 1.0f / l_[i];
        int qg = q0 + ty * 4 + i;
        float4 o = make_float4(ctx[i][0] * inv, ctx[i][1] * inv,
                               ctx[i][2] * inv, ctx[i][3] * inv);
        *(float4*)&O[((size_t)b * S_LEN + qg) * D_MODEL + h * HEAD_D + tx * 4] = o;
    }
}

// ---------------- host orchestration ----------------
extern "C" void kernel_launch(void* const* d_in, const int* in_sizes, int n_in,
                              void* d_out, int out_size)
{
    const float* x    = (const float*)d_in[0];
    const int*   mask = (const int*)  d_in[1];
    const float* wq = (const float*)d_in[2];
    const float* bq = (const float*)d_in[3];
    const float* wk = (const float*)d_in[4];
    const float* bk = (const float*)d_in[5];
    const float* wv = (const float*)d_in[6];
    const float* bv = (const float*)d_in[7];
    const float* wo = (const float*)d_in[8];
    const float* bo = (const float*)d_in[9];
    const float* w1 = (const float*)d_in[10];
    const float* b1 = (const float*)d_in[11];
    const float* w2 = (const float*)d_in[12];
    const float* b2 = (const float*)d_in[13];
    const float* g1  = (const float*)d_in[14];
    const float* be1 = (const float*)d_in[15];
    const float* g2  = (const float*)d_in[16];
    const float* be2 = (const float*)d_in[17];
    const float* bt  = (const float*)d_in[18];

    float *xn, *q, *k, *v, *ctx, *x1, *h;
    cudaGetSymbolAddress((void**)&xn,  g_xn);
    cudaGetSymbolAddress((void**)&q,   g_q);
    cudaGetSymbolAddress((void**)&k,   g_k);
    cudaGetSymbolAddress((void**)&v,   g_v);
    cudaGetSymbolAddress((void**)&ctx, g_ctx);
    cudaGetSymbolAddress((void**)&x1,  g_x1);
    cudaGetSymbolAddress((void**)&h,   g_h);

    float* out = (float*)d_out;

    // 1. pre-norm 1
    ln_kernel<<<N_TOK, 256>>>(x, g1, be1, xn);

    // 2. QKV projections
    dim3 gproj(D_MODEL / 128, N_TOK / 128);   // (8, 32)
    gemm_kernel<0><<<gproj, 256>>>(xn, wq, bq, nullptr, q, N_TOK, D_MODEL, D_MODEL);
    gemm_kernel<0><<<gproj, 256>>>(xn, wk, bk, nullptr, k, N_TOK, D_MODEL, D_MODEL);
    gemm_kernel<0><<<gproj, 256>>>(xn, wv, bv, nullptr, v, N_TOK, D_MODEL, D_MODEL);

    // 3. attention (flash, with rel-pos bias + mask)
    attn_kernel<<<dim3(S_LEN / 64, NUM_H, B_SZ), 256>>>(q, k, v, bt, mask, ctx);

    // 4. output projection + residual (x)
    gemm_kernel<2><<<gproj, 256>>>(ctx, wo, bo, x, x1, N_TOK, D_MODEL, D_MODEL);

    // 5. pre-norm 2
    ln_kernel<<<N_TOK, 256>>>(x1, g2, be2, xn);

    // 6. FFN up + GELU
    dim3 gffn1(FF_DIM / 128, N_TOK / 128);    // (32, 32)
    gemm_kernel<1><<<gffn1, 256>>>(xn, w1, b1, nullptr, h, N_TOK, FF_DIM, D_MODEL);

    // 7. FFN down + residual (x1) -> output
    gemm_kernel<2><<<gproj, 256>>>(h, w2, b2, x1, out, N_TOK, D_MODEL, FF_DIM);

    (void)in_sizes; (void)n_in; (void)out_size;
}

// round 3
// speedup vs baseline: 1.7670x; 1.7670x over previous
#include <cuda_runtime.h>
#include <cuda_bf16.h>
#include <math.h>
#include <stdint.h>

// ---------------- problem constants ----------------
#define B_SZ     2
#define S_LEN    2048
#define D_MODEL  1024
#define NUM_H    16
#define HEAD_D   64
#define FF_DIM   4096
#define N_TOK    (B_SZ * S_LEN)        // 4096
#define MAXM1    4999                  // MAX_SEQ_LEN - 1
#define MEG      (1024 * 1024)

// ---------------- scratch (static device globals; no allocation) ----------------
__device__ float g_xn [N_TOK * D_MODEL];
__device__ float g_q  [N_TOK * D_MODEL];
__device__ float g_k  [N_TOK * D_MODEL];
__device__ float g_v  [N_TOK * D_MODEL];
__device__ float g_ctx[N_TOK * D_MODEL];
__device__ float g_x1 [N_TOK * D_MODEL];
__device__ float g_h  [N_TOK * FF_DIM];
__device__ __nv_bfloat16 g_ahi[N_TOK * FF_DIM];
__device__ __nv_bfloat16 g_alo[N_TOK * FF_DIM];
__device__ __nv_bfloat16 g_whi[12 * MEG];
__device__ __nv_bfloat16 g_wlo[12 * MEG];

// ---------------- PTX helpers (portable: sm_80+ features only) ----------------
__device__ __forceinline__ uint32_t smem_u32(const void* p) {
    uint32_t a;
    asm("{ .reg .u64 t; cvta.to.shared.u64 t, %1; cvt.u32.u64 %0, t; }" : "=r"(a) : "l"(p));
    return a;
}

#define CP_ASYNC16(saddr, gptr) \
    asm volatile("cp.async.cg.shared.global [%0], [%1], 16;" :: "r"(saddr), "l"(gptr))
#define CP_COMMIT() asm volatile("cp.async.commit_group;" ::: "memory")
#define CP_WAIT(n)  asm volatile("cp.async.wait_group %0;" :: "n"(n) : "memory")

#define LDSM_X4(r0, r1, r2, r3, addr) \
    asm volatile("ldmatrix.sync.aligned.m8n8.x4.shared.b16 {%0,%1,%2,%3}, [%4];" \
                 : "=r"(r0), "=r"(r1), "=r"(r2), "=r"(r3) : "r"(addr))

__device__ __forceinline__ void mma16816(float* c, const uint32_t* a, const uint32_t* b) {
    asm volatile("mma.sync.aligned.m16n8k16.row.col.f32.bf16.bf16.f32 "
        "{%0,%1,%2,%3}, {%4,%5,%6,%7}, {%8,%9}, {%0,%1,%2,%3};"
        : "+f"(c[0]), "+f"(c[1]), "+f"(c[2]), "+f"(c[3])
        : "r"(a[0]), "r"(a[1]), "r"(a[2]), "r"(a[3]), "r"(b[0]), "r"(b[1]));
}

// ---------------- LayerNorm ----------------
__global__ __launch_bounds__(256) void ln_kernel(
    const float* __restrict__ x, const float* __restrict__ gamma,
    const float* __restrict__ beta, float* __restrict__ out)
{
    int row = blockIdx.x;
    int tid = threadIdx.x;
    const float4* xr = (const float4*)(x + (size_t)row * D_MODEL);
    float4 v = xr[tid];
    float s  = v.x + v.y + v.z + v.w;
    float ss = v.x*v.x + v.y*v.y + v.z*v.z + v.w*v.w;
    #pragma unroll
    for (int o = 16; o; o >>= 1) {
        s  += __shfl_xor_sync(0xffffffffu, s,  o);
        ss += __shfl_xor_sync(0xffffffffu, ss, o);
    }
    __shared__ float rs[8], rss[8];
    int w = tid >> 5;
    if ((tid & 31) == 0) { rs[w] = s; rss[w] = ss; }
    __syncthreads();
    float S0 = 0.f, SS0 = 0.f;
    #pragma unroll
    for (int i = 0; i < 8; i++) { S0 += rs[i]; SS0 += rss[i]; }
    float mean = S0 * (1.0f / D_MODEL);
    float var  = SS0 * (1.0f / D_MODEL) - mean * mean;
    float rstd = rsqrtf(var + 1e-5f);
    float4 gg = ((const float4*)gamma)[tid];
    float4 bb = ((const float4*)beta)[tid];
    float4 o;
    o.x = (v.x - mean) * rstd * gg.x + bb.x;
    o.y = (v.y - mean) * rstd * gg.y + bb.y;
    o.z = (v.z - mean) * rstd * gg.z + bb.z;
    o.w = (v.w - mean) * rstd * gg.w + bb.w;
    ((float4*)(out + (size_t)row * D_MODEL))[tid] = o;
}

// ---------------- fp32 -> bf16 hi/lo split ----------------
__global__ __launch_bounds__(256) void split_act(
    const float* __restrict__ in, __nv_bfloat16* __restrict__ hi,
    __nv_bfloat16* __restrict__ lo, int n4)
{
    int i = blockIdx.x * blockDim.x + threadIdx.x;
    if (i >= n4) return;
    float4 v = ((const float4*)in)[i];
    __nv_bfloat16 h0 = __float2bfloat16(v.x), h1 = __float2bfloat16(v.y);
    __nv_bfloat16 h2 = __float2bfloat16(v.z), h3 = __float2bfloat16(v.w);
    __nv_bfloat16 l0 = __float2bfloat16(v.x - __bfloat162float(h0));
    __nv_bfloat16 l1 = __float2bfloat16(v.y - __bfloat162float(h1));
    __nv_bfloat16 l2 = __float2bfloat16(v.z - __bfloat162float(h2));
    __nv_bfloat16 l3 = __float2bfloat16(v.w - __bfloat162float(h3));
    __nv_bfloat162 ha; ha.x = h0; ha.y = h1;
    __nv_bfloat162 hb; hb.x = h2; hb.y = h3;
    __nv_bfloat162 la; la.x = l0; la.y = l1;
    __nv_bfloat162 lb; lb.x = l2; lb.y = l3;
    uint2 hu = make_uint2(*(uint32_t*)&ha, *(uint32_t*)&hb);
    uint2 lu = make_uint2(*(uint32_t*)&la, *(uint32_t*)&lb);
    *(uint2*)&hi[(size_t)i * 4] = hu;
    *(uint2*)&lo[(size_t)i * 4] = lu;
}

// ---------------- weight split + transpose: w[K,N] fp32 -> hi/lo[N,K] bf16 ----------------
__global__ __launch_bounds__(256) void split_w(
    const float* __restrict__ w, __nv_bfloat16* __restrict__ hi,
    __nv_bfloat16* __restrict__ lo, int K, int N)
{
    __shared__ float tile[32][33];
    int n0 = blockIdx.x * 32, k0 = blockIdx.y * 32;
    int tx = threadIdx.x, ty = threadIdx.y;   // (32, 8)
    #pragma unroll
    for (int r = 0; r < 4; r++)
        tile[ty + 8 * r][tx] = w[(size_t)(k0 + ty + 8 * r) * N + n0 + tx];
    __syncthreads();
    #pragma unroll
    for (int r = 0; r < 4; r++) {
        float v = tile[tx][ty + 8 * r];
        size_t o = (size_t)(n0 + ty + 8 * r) * K + k0 + tx;
        __nv_bfloat16 h = __float2bfloat16(v);
        hi[o] = h;
        lo[o] = __float2bfloat16(v - __bfloat162float(h));
    }
}

// ---------------- mma.sync bf16-split GEMM ----------------
// C[M,N] = A[M,K] @ W[K,N] (W stored [N,K] hi/lo) + bias (+epilogue)
// EPI: 0 bias, 1 bias+GELU, 2 bias+residual
__device__ __forceinline__ float gelu_exact(float x) {
    return 0.5f * x * (1.0f + erff(x * 0.70710678118654752f));
}

// stage layout (bytes): Ahi 16K | Alo 16K | Bhi 16K | Blo 16K = 64K; 2 stages
#define GM_AHI   0
#define GM_ALO   16384
#define GM_BHI   32768
#define GM_BLO   49152
#define GM_SSZ   65536
#define GM_SMEM  (2 * GM_SSZ)

template<int EPI>
__global__ __launch_bounds__(256) void gemm_mma(
    const __nv_bfloat16* __restrict__ Ahi, const __nv_bfloat16* __restrict__ Alo,
    const __nv_bfloat16* __restrict__ Bhi, const __nv_bfloat16* __restrict__ Blo,
    const float* __restrict__ bias, const float* __restrict__ res,
    float* __restrict__ C, int M, int N, int K)
{
    extern __shared__ char smem[];
    uint32_t base = smem_u32(smem);
    int tid  = threadIdx.x;
    int lane = tid & 31;
    int wid  = tid >> 5;
    int warp_m = wid & 3;          // 4 warps along M (32 rows each)
    int warp_n = wid >> 2;         // 2 warps along N (64 cols each)
    int bm = blockIdx.y * 128, bn = blockIdx.x * 128;

    float acc[2][8][4];
    #pragma unroll
    for (int i = 0; i < 2; i++)
        #pragma unroll
        for (int j = 0; j < 8; j++)
            #pragma unroll
            for (int t = 0; t < 4; t++) acc[i][j][t] = 0.f;

    // ----- async tile loaders (SW128 swizzle: 128B rows) -----
    auto load_tile = [&](uint32_t sdst, const __nv_bfloat16* g, int rowBase, int k0) {
        #pragma unroll
        for (int i = 0; i < 4; i++) {
            int f = i * 256 + tid;          // 0..1023 16B transfers
            int row = f >> 3, c = f & 7;
            const __nv_bfloat16* gp = g + (size_t)(rowBase + row) * K + k0 + c * 8;
            uint32_t off = row * 128 + c * 16;
            uint32_t sw = off ^ ((off >> 3) & 0x70);
            CP_ASYNC16(sdst + sw, gp);
        }
    };
    auto load_chunk = [&](int stage, int k0) {
        uint32_t sb = base + stage * GM_SSZ;
        load_tile(sb + GM_AHI, Ahi, bm, k0);
        load_tile(sb + GM_ALO, Alo, bm, k0);
        load_tile(sb + GM_BHI, Bhi, bn, k0);
        load_tile(sb + GM_BLO, Blo, bn, k0);
        CP_COMMIT();
    };

    // ----- per-lane ldmatrix address components -----
    // A (x4): lanes 0-15 -> rows m0-15 (k-half 0), lanes 16-31 -> same rows (k-half 1)
    int a_row = warp_m * 32 + (lane & 15);      // + mf*16
    int a_kh  = lane >> 4;
    // B (x4): lanes 0-7: n0-7 kh0 | 8-15: n0-7 kh1 | 16-23: n8-15 kh0 | 24-31: n8-15 kh1
    int b_row = warp_n * 64 + ((lane >> 4) & 1) * 8 + (lane & 7);   // + nfp*16
    int b_kh  = (lane >> 3) & 1;

    int nCh = K >> 6;
    load_chunk(0, 0);

    for (int it = 0; it < nCh; it++) {
        int buf = it & 1;
        if (it + 1 < nCh) { load_chunk(buf ^ 1, (it + 1) << 6); CP_WAIT(1); }
        else              { CP_WAIT(0); }
        __syncthreads();

        uint32_t sb = base + buf * GM_SSZ;
        #pragma unroll
        for (int ks = 0; ks < 4; ks++) {
            // A fragments (hi & lo) for both m-frags
            uint32_t ah[2][4], al[2][4];
            #pragma unroll
            for (int mf = 0; mf < 2; mf++) {
                int row = a_row + mf * 16;
                uint32_t col = (uint32_t)((ks * 2 + a_kh) ^ (row & 7)) * 16;
                uint32_t ad = sb + GM_AHI + row * 128 + col;
                LDSM_X4(ah[mf][0], ah[mf][1], ah[mf][2], ah[mf][3], ad);
                ad = sb + GM_ALO + row * 128 + col;
                LDSM_X4(al[mf][0], al[mf][1], al[mf][2], al[mf][3], ad);
            }
            #pragma unroll
            for (int nfp = 0; nfp < 4; nfp++) {
                int row = b_row + nfp * 16;
                uint32_t col = (uint32_t)((ks * 2 + b_kh) ^ (row & 7)) * 16;
                uint32_t bh[4], bl[4];
                uint32_t bd = sb + GM_BHI + row * 128 + col;
                LDSM_X4(bh[0], bh[1], bh[2], bh[3], bd);
                bd = sb + GM_BLO + row * 128 + col;
                LDSM_X4(bl[0], bl[1], bl[2], bl[3], bd);
                #pragma unroll
                for (int mf = 0; mf < 2; mf++) {
                    #pragma unroll
                    for (int nn = 0; nn < 2; nn++) {
                        float* c = acc[mf][nfp * 2 + nn];
                        mma16816(c, ah[mf], &bh[nn * 2]);   // hi*hi
                        mma16816(c, ah[mf], &bl[nn * 2]);   // hi*lo
                        mma16816(c, al[mf], &bh[nn * 2]);   // lo*hi
                    }
                }
            }
        }
        __syncthreads();
    }

    // ----- epilogue: c0,c1 at (m, n..n+1), c2,c3 at (m+8, n..n+1) -----
    int mrow0 = bm + warp_m * 32 + (lane >> 2);
    int ncol0 = bn + warp_n * 64 + (lane & 3) * 2;
    #pragma unroll
    for (int mf = 0; mf < 2; mf++) {
        #pragma unroll
        for (int nf = 0; nf < 8; nf++) {
            int n = ncol0 + nf * 8;
            float b0 = bias[n], b1 = bias[n + 1];
            #pragma unroll
            for (int half = 0; half < 2; half++) {
                int m = mrow0 + mf * 16 + half * 8;
                float v0 = acc[mf][nf][half * 2 + 0] + b0;
                float v1 = acc[mf][nf][half * 2 + 1] + b1;
                if (EPI == 1) { v0 = gelu_exact(v0); v1 = gelu_exact(v1); }
                size_t o = (size_t)m * N + n;
                if (EPI == 2) {
                    float2 rv = *(const float2*)&res[o];
                    v0 += rv.x; v1 += rv.y;
                }
                *(float2*)&C[o] = make_float2(v0, v1);
            }
        }
    }
}

// ---------------- Flash attention (fp32 SIMT) ----------------
__global__ __launch_bounds__(256) void attn_kernel(
    const float* __restrict__ Q, const float* __restrict__ K,
    const float* __restrict__ V, const float* __restrict__ bt,
    const int* __restrict__ mask, float* __restrict__ O)
{
    __shared__ float Qt [64 * 64];
    __shared__ float KPt[64 * 64];
    __shared__ float Vs [64 * 64];

    int b  = blockIdx.z, h = blockIdx.y;
    int q0 = blockIdx.x * 64;
    int tid = threadIdx.x;
    int tx = tid & 15, ty = tid >> 4;

    const float* Qb = Q + ((size_t)b * S_LEN + q0) * D_MODEL + h * HEAD_D;
    const float* Kb = K + ((size_t)b * S_LEN) * D_MODEL + h * HEAD_D;
    const float* Vb = V + ((size_t)b * S_LEN) * D_MODEL + h * HEAD_D;

    #pragma unroll
    for (int l = 0; l < 4; l++) {
        int f  = tid + l * 256;
        int qq = f >> 4;
        int d4 = (f & 15) * 4;
        float4 v = *(const float4*)&Qb[(size_t)qq * D_MODEL + d4];
        Qt[(d4 + 0) * 64 + qq] = v.x;
        Qt[(d4 + 1) * 64 + qq] = v.y;
        Qt[(d4 + 2) * 64 + qq] = v.z;
        Qt[(d4 + 3) * 64 + qq] = v.w;
    }

    float m_[4], l_[4], ctx[4][4];
    #pragma unroll
    for (int i = 0; i < 4; i++) {
        m_[i] = -1e30f; l_[i] = 0.f;
        #pragma unroll
        for (int j = 0; j < 4; j++) ctx[i][j] = 0.f;
    }

    for (int kt = 0; kt < S_LEN / 64; kt++) {
        int k0 = kt * 64;
        __syncthreads();
        #pragma unroll
        for (int l = 0; l < 4; l++) {
            int f  = tid + l * 256;
            int kk = f >> 4;
            int d4 = (f & 15) * 4;
            float4 kv = *(const float4*)&Kb[(size_t)(k0 + kk) * D_MODEL + d4];
            KPt[(d4 + 0) * 64 + kk] = kv.x;
            KPt[(d4 + 1) * 64 + kk] = kv.y;
            KPt[(d4 + 2) * 64 + kk] = kv.z;
            KPt[(d4 + 3) * 64 + kk] = kv.w;
            float4 vv = *(const float4*)&Vb[(size_t)(k0 + kk) * D_MODEL + d4];
            *(float4*)&Vs[kk * 64 + d4] = vv;
        }
        __syncthreads();

        float sacc[4][4];
        #pragma unroll
        for (int i = 0; i < 4; i++)
            #pragma unroll
            for (int j = 0; j < 4; j++) sacc[i][j] = 0.f;

        #pragma unroll 8
        for (int d = 0; d < 64; d++) {
            float4 av = *(float4*)&Qt [d * 64 + ty * 4];
            float4 bb = *(float4*)&KPt[d * 64 + tx * 4];
            float a[4] = {av.x, av.y, av.z, av.w};
            float bq[4] = {bb.x, bb.y, bb.z, bb.w};
            #pragma unroll
            for (int i = 0; i < 4; i++)
                #pragma unroll
                for (int j = 0; j < 4; j++)
                    sacc[i][j] += a[i] * bq[j];
        }

        #pragma unroll
        for (int i = 0; i < 4; i++) {
            int qg = q0 + ty * 4 + i;
            #pragma unroll
            for (int j = 0; j < 4; j++) {
                int kg = k0 + tx * 4 + j;
                float sc = sacc[i][j] * 0.125f
                         + bt[(size_t)(kg - qg + MAXM1) * NUM_H + h];
                int mv = mask[((size_t)b * S_LEN + qg) * S_LEN + kg];
                sacc[i][j] = mv ? sc : -1e9f;
            }
        }

        __syncthreads();

        #pragma unroll
        for (int i = 0; i < 4; i++) {
            float tm = fmaxf(fmaxf(sacc[i][0], sacc[i][1]),
                             fmaxf(sacc[i][2], sacc[i][3]));
            #pragma unroll
            for (int o = 8; o; o >>= 1)
                tm = fmaxf(tm, __shfl_xor_sync(0xffffffffu, tm, o));
            float mn   = fmaxf(m_[i], tm);
            float corr = __expf(m_[i] - mn);
            float pr[4]; float rsum = 0.f;
            #pragma unroll
            for (int j = 0; j < 4; j++) {
                pr[j] = __expf(sacc[i][j] - mn);
                rsum += pr[j];
            }
            *(float4*)&KPt[(ty * 4 + i) * 64 + tx * 4] =
                make_float4(pr[0], pr[1], pr[2], pr[3]);
            #pragma unroll
            for (int o = 8; o; o >>= 1)
                rsum += __shfl_xor_sync(0xffffffffu, rsum, o);
            l_[i] = l_[i] * corr + rsum;
            m_[i] = mn;
            #pragma unroll
            for (int j = 0; j < 4; j++) ctx[i][j] *= corr;
        }
        __syncthreads();

        #pragma unroll 8
        for (int kk = 0; kk < 64; kk++) {
            float4 vv = *(const float4*)&Vs[kk * 64 + tx * 4];
            float vj[4] = {vv.x, vv.y, vv.z, vv.w};
            #pragma unroll
            for (int i = 0; i < 4; i++) {
                float p = KPt[(ty * 4 + i) * 64 + kk];
                #pragma unroll
                for (int j = 0; j < 4; j++)
                    ctx[i][j] += p * vj[j];
            }
        }
    }

    #pragma unroll
    for (int i = 0; i < 4; i++) {
        float inv = 1.0f / l_[i];
        int qg = q0 + ty * 4 + i;
        float4 o = make_float4(ctx[i][0] * inv, ctx[i][1] * inv,
                               ctx[i][2] * inv, ctx[i][3] * inv);
        *(float4*)&O[((size_t)b * S_LEN + qg) * D_MODEL + h * HEAD_D + tx * 4] = o;
    }
}

// ---------------- host orchestration ----------------
extern "C" void kernel_launch(void* const* d_in, const int* in_sizes, int n_in,
                              void* d_out, int out_size)
{
    const float* x    = (const float*)d_in[0];
    const int*   mask = (const int*)  d_in[1];
    const float* wq = (const float*)d_in[2];
    const float* bq = (const float*)d_in[3];
    const float* wk = (const float*)d_in[4];
    const float* bk = (const float*)d_in[5];
    const float* wv = (const float*)d_in[6];
    const float* bv = (const float*)d_in[7];
    const float* wo = (const float*)d_in[8];
    const float* bo = (const float*)d_in[9];
    const float* w1 = (const float*)d_in[10];
    const float* b1 = (const float*)d_in[11];
    const float* w2 = (const float*)d_in[12];
    const float* b2 = (const float*)d_in[13];
    const float* g1  = (const float*)d_in[14];
    const float* be1 = (const float*)d_in[15];
    const float* g2  = (const float*)d_in[16];
    const float* be2 = (const float*)d_in[17];
    const float* bt  = (const float*)d_in[18];

    float *xn, *q, *k, *v, *ctx, *x1, *h;
    __nv_bfloat16 *ahi, *alo, *whi, *wlo;
    cudaGetSymbolAddress((void**)&xn,  g_xn);
    cudaGetSymbolAddress((void**)&q,   g_q);
    cudaGetSymbolAddress((void**)&k,   g_k);
    cudaGetSymbolAddress((void**)&v,   g_v);
    cudaGetSymbolAddress((void**)&ctx, g_ctx);
    cudaGetSymbolAddress((void**)&x1,  g_x1);
    cudaGetSymbolAddress((void**)&h,   g_h);
    cudaGetSymbolAddress((void**)&ahi, g_ahi);
    cudaGetSymbolAddress((void**)&alo, g_alo);
    cudaGetSymbolAddress((void**)&whi, g_whi);
    cudaGetSymbolAddress((void**)&wlo, g_wlo);

    float* out = (float*)d_out;

    cudaFuncSetAttribute(gemm_mma<0>, cudaFuncAttributeMaxDynamicSharedMemorySize, GM_SMEM);
    cudaFuncSetAttribute(gemm_mma<1>, cudaFuncAttributeMaxDynamicSharedMemorySize, GM_SMEM);
    cudaFuncSetAttribute(gemm_mma<2>, cudaFuncAttributeMaxDynamicSharedMemorySize, GM_SMEM);

    dim3 tb(32, 8);
    // weight splits: [K,N] fp32 -> [N,K] bf16 hi/lo
    split_w<<<dim3(32, 32),  tb>>>(wq, whi + 0 * MEG, wlo + 0 * MEG, 1024, 1024);
    split_w<<<dim3(32, 32),  tb>>>(wk, whi + 1 * MEG, wlo + 1 * MEG, 1024, 1024);
    split_w<<<dim3(32, 32),  tb>>>(wv, whi + 2 * MEG, wlo + 2 * MEG, 1024, 1024);
    split_w<<<dim3(32, 32),  tb>>>(wo, whi + 3 * MEG, wlo + 3 * MEG, 1024, 1024);
    split_w<<<dim3(128, 32), tb>>>(w1, whi + 4 * MEG, wlo + 4 * MEG, 1024, 4096);
    split_w<<<dim3(32, 128), tb>>>(w2, whi + 8 * MEG, wlo + 8 * MEG, 4096, 1024);

    // 1. pre-norm 1
    ln_kernel<<<N_TOK, 256>>>(x, g1, be1, xn);
    split_act<<<(N_TOK * D_MODEL / 4 + 255) / 256, 256>>>(xn, ahi, alo, N_TOK * D_MODEL / 4);

    // 2. QKV projections
    dim3 gproj(D_MODEL / 128, N_TOK / 128);
    gemm_mma<0><<<gproj, 256, GM_SMEM>>>(ahi, alo, whi + 0 * MEG, wlo + 0 * MEG, bq, nullptr, q, N_TOK, D_MODEL, D_MODEL);
    gemm_mma<0><<<gproj, 256, GM_SMEM>>>(ahi, alo, whi + 1 * MEG, wlo + 1 * MEG, bk, nullptr, k, N_TOK, D_MODEL, D_MODEL);
    gemm_mma<0><<<gproj, 256, GM_SMEM>>>(ahi, alo, whi + 2 * MEG, wlo + 2 * MEG, bv, nullptr, v, N_TOK, D_MODEL, D_MODEL);

    // 3. attention
    attn_kernel<<<dim3(S_LEN / 64, NUM_H, B_SZ), 256>>>(q, k, v, bt, mask, ctx);

    // 4. output projection + residual(x)
    split_act<<<(N_TOK * D_MODEL / 4 + 255) / 256, 256>>>(ctx, ahi, alo, N_TOK * D_MODEL / 4);
    gemm_mma<2><<<gproj, 256, GM_SMEM>>>(ahi, alo, whi + 3 * MEG, wlo + 3 * MEG, bo, x, x1, N_TOK, D_MODEL, D_MODEL);

    // 5. pre-norm 2
    ln_kernel<<<N_TOK, 256>>>(x1, g2, be2, xn);
    split_act<<<(N_TOK * D_MODEL / 4 + 255) / 256, 256>>>(xn, ahi, alo, N_TOK * D_MODEL / 4);

    // 6. FFN up + GELU
    gemm_mma<1><<<dim3(FF_DIM / 128, N_TOK / 128), 256, GM_SMEM>>>(ahi, alo, whi + 4 * MEG, wlo + 4 * MEG, b1, nullptr, h, N_TOK, FF_DIM, D_MODEL);

    // 7. FFN down + residual(x1) -> out
    split_act<<<(N_TOK * FF_DIM / 4 + 255) / 256, 256>>>(h, ahi, alo, N_TOK * FF_DIM / 4);
    gemm_mma<2><<<gproj, 256, GM_SMEM>>>(ahi, alo, whi + 8 * MEG, wlo + 8 * MEG, b2, x1, out, N_TOK, D_MODEL, FF_DIM);

    (void)in_sizes; (void)n_in; (void)out_size;
}

// round 4
// speedup vs baseline: 3.4607x; 1.9585x over previous
#include <cuda_runtime.h>
#include <cuda_bf16.h>
#include <math.h>
#include <stdint.h>

// ---------------- problem constants ----------------
#define B_SZ     2
#define S_LEN    2048
#define D_MODEL  1024
#define NUM_H    16
#define HEAD_D   64
#define FF_DIM   4096
#define N_TOK    (B_SZ * S_LEN)        // 4096
#define MAXM1    4999                  // MAX_SEQ_LEN - 1
#define MEG      (1024 * 1024)

// ---------------- scratch (static device globals; no allocation) ----------------
__device__ float g_x1 [N_TOK * D_MODEL];
__device__ __nv_bfloat16 g_ahi[N_TOK * D_MODEL];
__device__ __nv_bfloat16 g_alo[N_TOK * D_MODEL];
__device__ __nv_bfloat16 g_qhi[N_TOK * D_MODEL];
__device__ __nv_bfloat16 g_qlo[N_TOK * D_MODEL];
__device__ __nv_bfloat16 g_khi[N_TOK * D_MODEL];
__device__ __nv_bfloat16 g_klo[N_TOK * D_MODEL];
__device__ __nv_bfloat16 g_vhi[N_TOK * D_MODEL];
__device__ __nv_bfloat16 g_vlo[N_TOK * D_MODEL];
__device__ __nv_bfloat16 g_chi[N_TOK * D_MODEL];
__device__ __nv_bfloat16 g_clo[N_TOK * D_MODEL];
__device__ __nv_bfloat16 g_hhi[N_TOK * FF_DIM];
__device__ __nv_bfloat16 g_hlo[N_TOK * FF_DIM];
__device__ __nv_bfloat16 g_whi[12 * MEG];
__device__ __nv_bfloat16 g_wlo[12 * MEG];
__device__ unsigned long long g_mpk[(size_t)B_SZ * S_LEN * (S_LEN / 64)];

// ---------------- PTX helpers (portable sm_80+ only) ----------------
__device__ __forceinline__ uint32_t smem_u32(const void* p) {
    uint32_t a;
    asm("{ .reg .u64 t; cvta.to.shared.u64 t, %1; cvt.u32.u64 %0, t; }" : "=r"(a) : "l"(p));
    return a;
}

#define CP_ASYNC16(saddr, gptr) \
    asm volatile("cp.async.cg.shared.global [%0], [%1], 16;" :: "r"(saddr), "l"(gptr))
#define CP_ASYNC4(saddr, gptr) \
    asm volatile("cp.async.ca.shared.global [%0], [%1], 4;" :: "r"(saddr), "l"(gptr))
#define CP_COMMIT() asm volatile("cp.async.commit_group;" ::: "memory")
#define CP_WAIT(n)  asm volatile("cp.async.wait_group %0;" :: "n"(n) : "memory")

#define LDSM_X4(r0, r1, r2, r3, addr) \
    asm volatile("ldmatrix.sync.aligned.m8n8.x4.shared.b16 {%0,%1,%2,%3}, [%4];" \
                 : "=r"(r0), "=r"(r1), "=r"(r2), "=r"(r3) : "r"(addr))
#define LDSM_X4_T(r0, r1, r2, r3, addr) \
    asm volatile("ldmatrix.sync.aligned.m8n8.x4.trans.shared.b16 {%0,%1,%2,%3}, [%4];" \
                 : "=r"(r0), "=r"(r1), "=r"(r2), "=r"(r3) : "r"(addr))

__device__ __forceinline__ void mma16816(float* c, const uint32_t* a, const uint32_t* b) {
    asm volatile("mma.sync.aligned.m16n8k16.row.col.f32.bf16.bf16.f32 "
        "{%0,%1,%2,%3}, {%4,%5,%6,%7}, {%8,%9}, {%0,%1,%2,%3};"
        : "+f"(c[0]), "+f"(c[1]), "+f"(c[2]), "+f"(c[3])
        : "r"(a[0]), "r"(a[1]), "r"(a[2]), "r"(a[3]), "r"(b[0]), "r"(b[1]));
}

__device__ __forceinline__ uint32_t pack_bf16(float a, float b) {
    __nv_bfloat162 t = __float22bfloat162_rn(make_float2(a, b));
    return *(uint32_t*)&t;
}
__device__ __forceinline__ void split2(float v0, float v1, uint32_t& hi, uint32_t& lo) {
    __nv_bfloat16 h0 = __float2bfloat16(v0), h1 = __float2bfloat16(v1);
    float r0 = v0 - __bfloat162float(h0), r1 = v1 - __bfloat162float(h1);
    hi = pack_bf16(__bfloat162float(h0), __bfloat162float(h1)); // exact re-pack
    __nv_bfloat162 H; H.x = h0; H.y = h1;
    hi = *(uint32_t*)&H;
    __nv_bfloat162 L; L.x = __float2bfloat16(r0); L.y = __float2bfloat16(r1);
    lo = *(uint32_t*)&L;
}

// ---------------- LayerNorm -> bf16 hi/lo ----------------
__global__ __launch_bounds__(256) void ln_kernel(
    const float* __restrict__ x, const float* __restrict__ gamma,
    const float* __restrict__ beta, __nv_bfloat16* __restrict__ hi,
    __nv_bfloat16* __restrict__ lo)
{
    int row = blockIdx.x;
    int tid = threadIdx.x;
    const float4* xr = (const float4*)(x + (size_t)row * D_MODEL);
    float4 v = xr[tid];
    float s  = v.x + v.y + v.z + v.w;
    float ss = v.x*v.x + v.y*v.y + v.z*v.z + v.w*v.w;
    #pragma unroll
    for (int o = 16; o; o >>= 1) {
        s  += __shfl_xor_sync(0xffffffffu, s,  o);
        ss += __shfl_xor_sync(0xffffffffu, ss, o);
    }
    __shared__ float rs[8], rss[8];
    int w = tid >> 5;
    if ((tid & 31) == 0) { rs[w] = s; rss[w] = ss; }
    __syncthreads();
    float S0 = 0.f, SS0 = 0.f;
    #pragma unroll
    for (int i = 0; i < 8; i++) { S0 += rs[i]; SS0 += rss[i]; }
    float mean = S0 * (1.0f / D_MODEL);
    float var  = SS0 * (1.0f / D_MODEL) - mean * mean;
    float rstd = rsqrtf(var + 1e-5f);
    float4 gg = ((const float4*)gamma)[tid];
    float4 bb = ((const float4*)beta)[tid];
    float o0 = (v.x - mean) * rstd * gg.x + bb.x;
    float o1 = (v.y - mean) * rstd * gg.y + bb.y;
    float o2 = (v.z - mean) * rstd * gg.z + bb.z;
    float o3 = (v.w - mean) * rstd * gg.w + bb.w;
    uint32_t h0, l0, h1, l1;
    split2(o0, o1, h0, l0);
    split2(o2, o3, h1, l1);
    size_t base = (size_t)row * D_MODEL + tid * 4;
    *(uint2*)&hi[base] = make_uint2(h0, h1);
    *(uint2*)&lo[base] = make_uint2(l0, l1);
}

// ---------------- weight split + transpose: w[K,N] fp32 -> hi/lo[N,K] bf16 ----------------
__global__ __launch_bounds__(256) void split_w(
    const float* __restrict__ w, __nv_bfloat16* __restrict__ hi,
    __nv_bfloat16* __restrict__ lo, int K, int N)
{
    __shared__ float tile[32][33];
    int n0 = blockIdx.x * 32, k0 = blockIdx.y * 32;
    int tx = threadIdx.x, ty = threadIdx.y;   // (32, 8)
    #pragma unroll
    for (int r = 0; r < 4; r++)
        tile[ty + 8 * r][tx] = w[(size_t)(k0 + ty + 8 * r) * N + n0 + tx];
    __syncthreads();
    #pragma unroll
    for (int r = 0; r < 4; r++) {
        float v = tile[tx][ty + 8 * r];
        size_t o = (size_t)(n0 + ty + 8 * r) * K + k0 + tx;
        __nv_bfloat16 h = __float2bfloat16(v);
        hi[o] = h;
        lo[o] = __float2bfloat16(v - __bfloat162float(h));
    }
}

// ---------------- mask pack: 64 ints -> 1 uint64 bitmask ----------------
__global__ __launch_bounds__(256) void mask_pack(
    const int* __restrict__ m, unsigned long long* __restrict__ pk, int total)
{
    int idx = blockIdx.x * 256 + threadIdx.x;
    if (idx >= total) return;
    const int4* p = (const int4*)m + (size_t)idx * 16;
    unsigned long long w = 0;
    #pragma unroll
    for (int i = 0; i < 16; i++) {
        int4 v = p[i];
        w |= (unsigned long long)(v.x != 0) << (i * 4 + 0);
        w |= (unsigned long long)(v.y != 0) << (i * 4 + 1);
        w |= (unsigned long long)(v.z != 0) << (i * 4 + 2);
        w |= (unsigned long long)(v.w != 0) << (i * 4 + 3);
    }
    pk[idx] = w;
}

// ---------------- mma.sync bf16-split GEMM ----------------
// EPI: 1 bias+GELU -> hi/lo, 2 bias+residual -> fp32, 3 bias -> hi/lo
__device__ __forceinline__ float gelu_exact(float x) {
    return 0.5f * x * (1.0f + erff(x * 0.70710678118654752f));
}

#define GM_AHI   0
#define GM_ALO   16384
#define GM_BHI   32768
#define GM_BLO   49152
#define GM_SSZ   65536
#define GM_SMEM  (2 * GM_SSZ)

template<int EPI>
__global__ __launch_bounds__(256) void gemm_mma(
    const __nv_bfloat16* __restrict__ Ahi, const __nv_bfloat16* __restrict__ Alo,
    const __nv_bfloat16* __restrict__ Bhi, const __nv_bfloat16* __restrict__ Blo,
    const float* __restrict__ bias, const float* __restrict__ res,
    float* __restrict__ C, __nv_bfloat16* __restrict__ Chi,
    __nv_bfloat16* __restrict__ Clo, int M, int N, int K)
{
    extern __shared__ char smem[];
    uint32_t base = smem_u32(smem);
    int tid  = threadIdx.x;
    int lane = tid & 31;
    int wid  = tid >> 5;
    int warp_m = wid & 3;
    int warp_n = wid >> 2;
    int bm = blockIdx.y * 128, bn = blockIdx.x * 128;

    float acc[2][8][4];
    #pragma unroll
    for (int i = 0; i < 2; i++)
        #pragma unroll
        for (int j = 0; j < 8; j++)
            #pragma unroll
            for (int t = 0; t < 4; t++) acc[i][j][t] = 0.f;

    auto load_tile = [&](uint32_t sdst, const __nv_bfloat16* g, int rowBase, int k0) {
        #pragma unroll
        for (int i = 0; i < 4; i++) {
            int f = i * 256 + tid;
            int row = f >> 3, c = f & 7;
            const __nv_bfloat16* gp = g + (size_t)(rowBase + row) * K + k0 + c * 8;
            uint32_t off = row * 128 + c * 16;
            uint32_t sw = off ^ ((off >> 3) & 0x70);
            CP_ASYNC16(sdst + sw, gp);
        }
    };
    auto load_chunk = [&](int stage, int k0) {
        uint32_t sb = base + stage * GM_SSZ;
        load_tile(sb + GM_AHI, Ahi, bm, k0);
        load_tile(sb + GM_ALO, Alo, bm, k0);
        load_tile(sb + GM_BHI, Bhi, bn, k0);
        load_tile(sb + GM_BLO, Blo, bn, k0);
        CP_COMMIT();
    };

    int a_row = warp_m * 32 + (lane & 15);
    int a_kh  = lane >> 4;
    int b_row = warp_n * 64 + ((lane >> 4) & 1) * 8 + (lane & 7);
    int b_kh  = (lane >> 3) & 1;

    int nCh = K >> 6;
    load_chunk(0, 0);

    for (int it = 0; it < nCh; it++) {
        int buf = it & 1;
        if (it + 1 < nCh) { load_chunk(buf ^ 1, (it + 1) << 6); CP_WAIT(1); }
        else              { CP_WAIT(0); }
        __syncthreads();

        uint32_t sb = base + buf * GM_SSZ;
        #pragma unroll
        for (int ks = 0; ks < 4; ks++) {
            uint32_t ah[2][4], al[2][4];
            #pragma unroll
            for (int mf = 0; mf < 2; mf++) {
                int row = a_row + mf * 16;
                uint32_t col = (uint32_t)((ks * 2 + a_kh) ^ (row & 7)) * 16;
                uint32_t ad = sb + GM_AHI + row * 128 + col;
                LDSM_X4(ah[mf][0], ah[mf][1], ah[mf][2], ah[mf][3], ad);
                ad = sb + GM_ALO + row * 128 + col;
                LDSM_X4(al[mf][0], al[mf][1], al[mf][2], al[mf][3], ad);
            }
            #pragma unroll
            for (int nfp = 0; nfp < 4; nfp++) {
                int row = b_row + nfp * 16;
                uint32_t col = (uint32_t)((ks * 2 + b_kh) ^ (row & 7)) * 16;
                uint32_t bh[4], bl[4];
                uint32_t bd = sb + GM_BHI + row * 128 + col;
                LDSM_X4(bh[0], bh[1], bh[2], bh[3], bd);
                bd = sb + GM_BLO + row * 128 + col;
                LDSM_X4(bl[0], bl[1], bl[2], bl[3], bd);
                #pragma unroll
                for (int mf = 0; mf < 2; mf++) {
                    #pragma unroll
                    for (int nn = 0; nn < 2; nn++) {
                        float* c = acc[mf][nfp * 2 + nn];
                        mma16816(c, ah[mf], &bh[nn * 2]);
                        mma16816(c, ah[mf], &bl[nn * 2]);
                        mma16816(c, al[mf], &bh[nn * 2]);
                    }
                }
            }
        }
        __syncthreads();
    }

    int mrow0 = bm + warp_m * 32 + (lane >> 2);
    int ncol0 = bn + warp_n * 64 + (lane & 3) * 2;
    #pragma unroll
    for (int mf = 0; mf < 2; mf++) {
        #pragma unroll
        for (int nf = 0; nf < 8; nf++) {
            int n = ncol0 + nf * 8;
            float b0 = bias[n], b1 = bias[n + 1];
            #pragma unroll
            for (int half = 0; half < 2; half++) {
                int m = mrow0 + mf * 16 + half * 8;
                float v0 = acc[mf][nf][half * 2 + 0] + b0;
                float v1 = acc[mf][nf][half * 2 + 1] + b1;
                size_t o = (size_t)m * N + n;
                if (EPI == 1) { v0 = gelu_exact(v0); v1 = gelu_exact(v1); }
                if (EPI == 2) {
                    float2 rv = *(const float2*)&res[o];
                    v0 += rv.x; v1 += rv.y;
                    *(float2*)&C[o] = make_float2(v0, v1);
                } else {
                    uint32_t hw, lw;
                    split2(v0, v1, hw, lw);
                    *(uint32_t*)&Chi[o] = hw;
                    *(uint32_t*)&Clo[o] = lw;
                }
            }
        }
    }
}

// ---------------- flash attention on mma.sync ----------------
// grid (S/64, H, B), block 128 (4 warps x m16). Scores: split QK (3 mma), PV: bf16.
#define AT_QHI   0
#define AT_QLO   8192
#define AT_ST    16384
#define AT_KH    0
#define AT_KL    8192
#define AT_V     16384
#define AT_BIAS  24576
#define AT_SSZ   25600
#define AT_SMEM  (AT_ST + 2 * AT_SSZ)

__global__ __launch_bounds__(128) void attn_mma(
    const __nv_bfloat16* __restrict__ Qhi, const __nv_bfloat16* __restrict__ Qlo,
    const __nv_bfloat16* __restrict__ Khi, const __nv_bfloat16* __restrict__ Klo,
    const __nv_bfloat16* __restrict__ Vhi, const float* __restrict__ bt,
    const unsigned long long* __restrict__ mpk,
    __nv_bfloat16* __restrict__ Ohi, __nv_bfloat16* __restrict__ Olo)
{
    extern __shared__ char smem[];
    uint32_t base = smem_u32(smem);
    const float* bias_sm = (const float*)(smem);   // typed view helper (offsets added manually)

    int b  = blockIdx.z, h = blockIdx.y;
    int q0 = blockIdx.x * 64;
    int tid  = threadIdx.x;
    int lane = tid & 31;
    int wid  = tid >> 5;
    size_t headoff = (size_t)h * HEAD_D;

    // ---- Q tile load (64 x 64, hi+lo) ----
    #pragma unroll
    for (int i = 0; i < 4; i++) {
        int f = i * 128 + tid;            // 0..511
        int row = f >> 3, c = f & 7;
        uint32_t sw = row * 128 + (uint32_t)((c ^ (row & 7)) * 16);
        const __nv_bfloat16* gp = Qhi + ((size_t)(b * S_LEN + q0 + row)) * D_MODEL + headoff + c * 8;
        CP_ASYNC16(base + AT_QHI + sw, gp);
        gp = Qlo + ((size_t)(b * S_LEN + q0 + row)) * D_MODEL + headoff + c * 8;
        CP_ASYNC16(base + AT_QLO + sw, gp);
    }
    CP_COMMIT();

    auto load_kv = [&](int s, int kt) {
        uint32_t sb = base + AT_ST + s * AT_SSZ;
        int kr = kt * 64;
        #pragma unroll
        for (int i = 0; i < 4; i++) {
            int f = i * 128 + tid;
            int row = f >> 3, c = f & 7;
            uint32_t sw = row * 128 + (uint32_t)((c ^ (row & 7)) * 16);
            size_t gb = ((size_t)(b * S_LEN + kr + row)) * D_MODEL + headoff + c * 8;
            CP_ASYNC16(sb + AT_KH + sw, Khi + gb);
            CP_ASYNC16(sb + AT_KL + sw, Klo + gb);
            CP_ASYNC16(sb + AT_V  + sw, Vhi + gb);
        }
        // bias diag band: idx i -> rel = (kr - q0 + i - 63) + MAXM1
        int d = kr - q0 + tid - 63 + MAXM1;
        CP_ASYNC4(sb + AT_BIAS + tid * 4, bt + (size_t)d * NUM_H + h);
        CP_COMMIT();
    };

    load_kv(0, 0);
    CP_WAIT(0);
    __syncthreads();

    // ---- hoist Q fragments ----
    int a_row = wid * 16 + (lane & 15);
    int a_kh  = lane >> 4;
    uint32_t qh[4][4], ql[4][4];
    #pragma unroll
    for (int ks = 0; ks < 4; ks++) {
        uint32_t col = (uint32_t)(((ks * 2 + a_kh) ^ (a_row & 7)) * 16);
        uint32_t ad = base + AT_QHI + a_row * 128 + col;
        LDSM_X4(qh[ks][0], qh[ks][1], qh[ks][2], qh[ks][3], ad);
        ad = base + AT_QLO + a_row * 128 + col;
        LDSM_X4(ql[ks][0], ql[ks][1], ql[ks][2], ql[ks][3], ad);
    }

    float ctx[8][4];
    #pragma unroll
    for (int i = 0; i < 8; i++)
        #pragma unroll
        for (int j = 0; j < 4; j++) ctx[i][j] = 0.f;
    float m0 = -3.0e38f, m1 = -3.0e38f, l0 = 0.f, l1 = 0.f;

    int r_loc0 = wid * 16 + (lane >> 2);        // local q row (0..63)
    int cbase  = (lane & 3) * 2;
    int b_row_base = ((lane >> 4) & 1) * 8 + (lane & 7);
    int b_kh = (lane >> 3) & 1;
    int v_i  = lane >> 3, v_j = lane & 7;

    const int nKT = S_LEN / 64;
    for (int kt = 0; kt < nKT; kt++) {
        int s = kt & 1;
        if (kt + 1 < nKT) { load_kv(s ^ 1, kt + 1); CP_WAIT(1); }
        else              { CP_WAIT(0); }
        __syncthreads();
        uint32_t sb = base + AT_ST + s * AT_SSZ;

        // prefetch mask words
        unsigned long long mw0 = mpk[((size_t)(b * S_LEN) + q0 + r_loc0) * nKT + kt];
        unsigned long long mw1 = mpk[((size_t)(b * S_LEN) + q0 + r_loc0 + 8) * nKT + kt];

        // ---- scores ----
        float sacc[8][4];
        #pragma unroll
        for (int i = 0; i < 8; i++)
            #pragma unroll
            for (int j = 0; j < 4; j++) sacc[i][j] = 0.f;

        #pragma unroll
        for (int ks = 0; ks < 4; ks++) {
            #pragma unroll
            for (int g = 0; g < 4; g++) {
                int row = g * 16 + b_row_base;
                uint32_t col = (uint32_t)(((ks * 2 + b_kh) ^ (row & 7)) * 16);
                uint32_t bh[4], bl[4];
                uint32_t bd = sb + AT_KH + row * 128 + col;
                LDSM_X4(bh[0], bh[1], bh[2], bh[3], bd);
                bd = sb + AT_KL + row * 128 + col;
                LDSM_X4(bl[0], bl[1], bl[2], bl[3], bd);
                mma16816(sacc[2*g],   qh[ks], &bh[0]);
                mma16816(sacc[2*g+1], qh[ks], &bh[2]);
                mma16816(sacc[2*g],   qh[ks], &bl[0]);
                mma16816(sacc[2*g+1], qh[ks], &bl[2]);
                mma16816(sacc[2*g],   ql[ks], &bh[0]);
                mma16816(sacc[2*g+1], ql[ks], &bh[2]);
            }
        }

        // ---- scale + bias + mask + online softmax ----
        const float* bs = (const float*)(smem + AT_ST + s * AT_SSZ + AT_BIAS);
        float mx0 = -3.0e38f, mx1 = -3.0e38f;
        #pragma unroll
        for (int f = 0; f < 8; f++) {
            int c0 = f * 8 + cbase;
            int i0 = c0 - r_loc0 + 63;
            float s00 = ((mw0 >> c0) & 1) ? sacc[f][0] * 0.125f + bs[i0]     : -1e9f;
            float s01 = ((mw0 >> (c0+1)) & 1) ? sacc[f][1] * 0.125f + bs[i0+1] : -1e9f;
            float s10 = ((mw1 >> c0) & 1) ? sacc[f][2] * 0.125f + bs[i0-8]   : -1e9f;
            float s11 = ((mw1 >> (c0+1)) & 1) ? sacc[f][3] * 0.125f + bs[i0-7] : -1e9f;
            sacc[f][0] = s00; sacc[f][1] = s01; sacc[f][2] = s10; sacc[f][3] = s11;
            mx0 = fmaxf(mx0, fmaxf(s00, s01));
            mx1 = fmaxf(mx1, fmaxf(s10, s11));
        }
        mx0 = fmaxf(mx0, __shfl_xor_sync(0xffffffffu, mx0, 1));
        mx0 = fmaxf(mx0, __shfl_xor_sync(0xffffffffu, mx0, 2));
        mx1 = fmaxf(mx1, __shfl_xor_sync(0xffffffffu, mx1, 1));
        mx1 = fmaxf(mx1, __shfl_xor_sync(0xffffffffu, mx1, 2));

        float mn0 = fmaxf(m0, mx0), mn1 = fmaxf(m1, mx1);
        float corr0 = __expf(m0 - mn0), corr1 = __expf(m1 - mn1);
        float rs0 = 0.f, rs1 = 0.f;
        #pragma unroll
        for (int f = 0; f < 8; f++) {
            float p00 = __expf(sacc[f][0] - mn0);
            float p01 = __expf(sacc[f][1] - mn0);
            float p10 = __expf(sacc[f][2] - mn1);
            float p11 = __expf(sacc[f][3] - mn1);
            sacc[f][0] = p00; sacc[f][1] = p01; sacc[f][2] = p10; sacc[f][3] = p11;
            rs0 += p00 + p01; rs1 += p10 + p11;
        }
        rs0 += __shfl_xor_sync(0xffffffffu, rs0, 1);
        rs0 += __shfl_xor_sync(0xffffffffu, rs0, 2);
        rs1 += __shfl_xor_sync(0xffffffffu, rs1, 1);
        rs1 += __shfl_xor_sync(0xffffffffu, rs1, 2);
        l0 = l0 * corr0 + rs0; m0 = mn0;
        l1 = l1 * corr1 + rs1; m1 = mn1;
        #pragma unroll
        for (int nf = 0; nf < 8; nf++) {
            ctx[nf][0] *= corr0; ctx[nf][1] *= corr0;
            ctx[nf][2] *= corr1; ctx[nf][3] *= corr1;
        }

        // ---- PV ----
        #pragma unroll
        for (int ks = 0; ks < 4; ks++) {
            uint32_t pf[4];
            pf[0] = pack_bf16(sacc[2*ks][0],   sacc[2*ks][1]);
            pf[1] = pack_bf16(sacc[2*ks][2],   sacc[2*ks][3]);
            pf[2] = pack_bf16(sacc[2*ks+1][0], sacc[2*ks+1][1]);
            pf[3] = pack_bf16(sacc[2*ks+1][2], sacc[2*ks+1][3]);
            #pragma unroll
            for (int vg = 0; vg < 4; vg++) {
                int row = ks * 16 + (v_i & 1) * 8 + v_j;
                uint32_t chunk = (uint32_t)(vg * 2 + (v_i >> 1));
                uint32_t vd = sb + AT_V + row * 128 + ((chunk ^ (row & 7)) * 16);
                uint32_t vb[4];
                LDSM_X4_T(vb[0], vb[1], vb[2], vb[3], vd);
                mma16816(ctx[2*vg],   pf, &vb[0]);
                mma16816(ctx[2*vg+1], pf, &vb[2]);
            }
        }
        __syncthreads();
    }

    // ---- finalize + write hi/lo ----
    float inv0 = 1.0f / l0, inv1 = 1.0f / l1;
    size_t tok0 = (size_t)(b * S_LEN + q0 + r_loc0);
    #pragma unroll
    for (int nf = 0; nf < 8; nf++) {
        int col = (int)headoff + nf * 8 + cbase;
        float v0 = ctx[nf][0] * inv0, v1 = ctx[nf][1] * inv0;
        uint32_t hw, lw;
        split2(v0, v1, hw, lw);
        *(uint32_t*)&Ohi[tok0 * D_MODEL + col] = hw;
        *(uint32_t*)&Olo[tok0 * D_MODEL + col] = lw;
        v0 = ctx[nf][2] * inv1; v1 = ctx[nf][3] * inv1;
        split2(v0, v1, hw, lw);
        *(uint32_t*)&Ohi[(tok0 + 8) * D_MODEL + col] = hw;
        *(uint32_t*)&Olo[(tok0 + 8) * D_MODEL + col] = lw;
    }
    (void)bias_sm;
}

// ---------------- host orchestration ----------------
extern "C" void kernel_launch(void* const* d_in, const int* in_sizes, int n_in,
                              void* d_out, int out_size)
{
    const float* x    = (const float*)d_in[0];
    const int*   mask = (const int*)  d_in[1];
    const float* wq = (const float*)d_in[2];
    const float* bq = (const float*)d_in[3];
    const float* wk = (const float*)d_in[4];
    const float* bk = (const float*)d_in[5];
    const float* wv = (const float*)d_in[6];
    const float* bv = (const float*)d_in[7];
    const float* wo = (const float*)d_in[8];
    const float* bo = (const float*)d_in[9];
    const float* w1 = (const float*)d_in[10];
    const float* b1 = (const float*)d_in[11];
    const float* w2 = (const float*)d_in[12];
    const float* b2 = (const float*)d_in[13];
    const float* g1  = (const float*)d_in[14];
    const float* be1 = (const float*)d_in[15];
    const float* g2  = (const float*)d_in[16];
    const float* be2 = (const float*)d_in[17];
    const float* bt  = (const float*)d_in[18];

    float* x1;
    __nv_bfloat16 *ahi, *alo, *qhi, *qlo, *khi, *klo, *vhi, *vlo, *chi, *clo, *hhi, *hlo, *whi, *wlo;
    unsigned long long* mpk;
    cudaGetSymbolAddress((void**)&x1,  g_x1);
    cudaGetSymbolAddress((void**)&ahi, g_ahi);
    cudaGetSymbolAddress((void**)&alo, g_alo);
    cudaGetSymbolAddress((void**)&qhi, g_qhi);
    cudaGetSymbolAddress((void**)&qlo, g_qlo);
    cudaGetSymbolAddress((void**)&khi, g_khi);
    cudaGetSymbolAddress((void**)&klo, g_klo);
    cudaGetSymbolAddress((void**)&vhi, g_vhi);
    cudaGetSymbolAddress((void**)&vlo, g_vlo);
    cudaGetSymbolAddress((void**)&chi, g_chi);
    cudaGetSymbolAddress((void**)&clo, g_clo);
    cudaGetSymbolAddress((void**)&hhi, g_hhi);
    cudaGetSymbolAddress((void**)&hlo, g_hlo);
    cudaGetSymbolAddress((void**)&whi, g_whi);
    cudaGetSymbolAddress((void**)&wlo, g_wlo);
    cudaGetSymbolAddress((void**)&mpk, g_mpk);

    float* out = (float*)d_out;

    cudaFuncSetAttribute(gemm_mma<1>, cudaFuncAttributeMaxDynamicSharedMemorySize, GM_SMEM);
    cudaFuncSetAttribute(gemm_mma<2>, cudaFuncAttributeMaxDynamicSharedMemorySize, GM_SMEM);
    cudaFuncSetAttribute(gemm_mma<3>, cudaFuncAttributeMaxDynamicSharedMemorySize, GM_SMEM);
    cudaFuncSetAttribute(attn_mma,    cudaFuncAttributeMaxDynamicSharedMemorySize, AT_SMEM);

    dim3 tb(32, 8);
    split_w<<<dim3(32, 32),  tb>>>(wq, whi + 0 * MEG, wlo + 0 * MEG, 1024, 1024);
    split_w<<<dim3(32, 32),  tb>>>(wk, whi + 1 * MEG, wlo + 1 * MEG, 1024, 1024);
    split_w<<<dim3(32, 32),  tb>>>(wv, whi + 2 * MEG, wlo + 2 * MEG, 1024, 1024);
    split_w<<<dim3(32, 32),  tb>>>(wo, whi + 3 * MEG, wlo + 3 * MEG, 1024, 1024);
    split_w<<<dim3(128, 32), tb>>>(w1, whi + 4 * MEG, wlo + 4 * MEG, 1024, 4096);
    split_w<<<dim3(32, 128), tb>>>(w2, whi + 8 * MEG, wlo + 8 * MEG, 4096, 1024);
    mask_pack<<<(B_SZ * S_LEN * (S_LEN / 64)) / 256, 256>>>(mask, mpk, B_SZ * S_LEN * (S_LEN / 64));

    // 1. pre-norm 1 -> hi/lo
    ln_kernel<<<N_TOK, 256>>>(x, g1, be1, ahi, alo);

    // 2. QKV projections -> bf16 hi/lo
    dim3 gproj(D_MODEL / 128, N_TOK / 128);
    gemm_mma<3><<<gproj, 256, GM_SMEM>>>(ahi, alo, whi + 0 * MEG, wlo + 0 * MEG, bq, nullptr, nullptr, qhi, qlo, N_TOK, D_MODEL, D_MODEL);
    gemm_mma<3><<<gproj, 256, GM_SMEM>>>(ahi, alo, whi + 1 * MEG, wlo + 1 * MEG, bk, nullptr, nullptr, khi, klo, N_TOK, D_MODEL, D_MODEL);
    gemm_mma<3><<<gproj, 256, GM_SMEM>>>(ahi, alo, whi + 2 * MEG, wlo + 2 * MEG, bv, nullptr, nullptr, vhi, vlo, N_TOK, D_MODEL, D_MODEL);

    // 3. attention
    attn_mma<<<dim3(S_LEN / 64, NUM_H, B_SZ), 128, AT_SMEM>>>(qhi, qlo, khi, klo, vhi, bt, mpk, chi, clo);

    // 4. output projection + residual(x) -> x1 fp32
    gemm_mma<2><<<gproj, 256, GM_SMEM>>>(chi, clo, whi + 3 * MEG, wlo + 3 * MEG, bo, x, x1, nullptr, nullptr, N_TOK, D_MODEL, D_MODEL);

    // 5. pre-norm 2 -> hi/lo
    ln_kernel<<<N_TOK, 256>>>(x1, g2, be2, ahi, alo);

    // 6. FFN up + GELU -> h hi/lo
    gemm_mma<1><<<dim3(FF_DIM / 128, N_TOK / 128), 256, GM_SMEM>>>(ahi, alo, whi + 4 * MEG, wlo + 4 * MEG, b1, nullptr, nullptr, hhi, hlo, N_TOK, FF_DIM, D_MODEL);

    // 7. FFN down + residual(x1) -> out
    gemm_mma<2><<<gproj, 256, GM_SMEM>>>(hhi, hlo, whi + 8 * MEG, wlo + 8 * MEG, b2, x1, out, nullptr, nullptr, N_TOK, D_MODEL, FF_DIM);

    (void)in_sizes; (void)n_in; (void)out_size;
}

// round 5
// speedup vs baseline: 4.7302x; 1.3668x over previous
#include <cuda_runtime.h>
#include <cuda_fp16.h>
#include <math.h>
#include <stdint.h>

// ---------------- problem constants ----------------
#define B_SZ     2
#define S_LEN    2048
#define D_MODEL  1024
#define NUM_H    16
#define HEAD_D   64
#define FF_DIM   4096
#define N_TOK    (B_SZ * S_LEN)        // 4096
#define MAXM1    4999                  // MAX_SEQ_LEN - 1
#define MEG      (1024 * 1024)

// ---------------- scratch (static device globals; no allocation) ----------------
__device__ float  g_x1 [N_TOK * D_MODEL];
__device__ __half g_ahi[N_TOK * D_MODEL];
__device__ __half g_alo[N_TOK * D_MODEL];
__device__ __half g_qhi[N_TOK * D_MODEL];
__device__ __half g_qlo[N_TOK * D_MODEL];
__device__ __half g_khi[N_TOK * D_MODEL];
__device__ __half g_vhi[N_TOK * D_MODEL];
__device__ __half g_chi[N_TOK * D_MODEL];
__device__ __half g_clo[N_TOK * D_MODEL];
__device__ __half g_hhi[N_TOK * FF_DIM];
__device__ __half g_hlo[N_TOK * FF_DIM];
__device__ __half g_w  [12 * MEG];
__device__ unsigned long long g_mpk[(size_t)B_SZ * S_LEN * (S_LEN / 64)];

// ---------------- PTX helpers (portable sm_80+ only) ----------------
__device__ __forceinline__ uint32_t smem_u32(const void* p) {
    uint32_t a;
    asm("{ .reg .u64 t; cvta.to.shared.u64 t, %1; cvt.u32.u64 %0, t; }" : "=r"(a) : "l"(p));
    return a;
}

#define CP_ASYNC16(saddr, gptr) \
    asm volatile("cp.async.cg.shared.global [%0], [%1], 16;" :: "r"(saddr), "l"(gptr))
#define CP_ASYNC4(saddr, gptr) \
    asm volatile("cp.async.ca.shared.global [%0], [%1], 4;" :: "r"(saddr), "l"(gptr))
#define CP_COMMIT() asm volatile("cp.async.commit_group;" ::: "memory")
#define CP_WAIT(n)  asm volatile("cp.async.wait_group %0;" :: "n"(n) : "memory")

#define LDSM_X4(r0, r1, r2, r3, addr) \
    asm volatile("ldmatrix.sync.aligned.m8n8.x4.shared.b16 {%0,%1,%2,%3}, [%4];" \
                 : "=r"(r0), "=r"(r1), "=r"(r2), "=r"(r3) : "r"(addr))
#define LDSM_X4_T(r0, r1, r2, r3, addr) \
    asm volatile("ldmatrix.sync.aligned.m8n8.x4.trans.shared.b16 {%0,%1,%2,%3}, [%4];" \
                 : "=r"(r0), "=r"(r1), "=r"(r2), "=r"(r3) : "r"(addr))

__device__ __forceinline__ void mma16816(float* c, const uint32_t* a, const uint32_t* b) {
    asm volatile("mma.sync.aligned.m16n8k16.row.col.f32.f16.f16.f32 "
        "{%0,%1,%2,%3}, {%4,%5,%6,%7}, {%8,%9}, {%0,%1,%2,%3};"
        : "+f"(c[0]), "+f"(c[1]), "+f"(c[2]), "+f"(c[3])
        : "r"(a[0]), "r"(a[1]), "r"(a[2]), "r"(a[3]), "r"(b[0]), "r"(b[1]));
}

__device__ __forceinline__ uint32_t pack_h(float a, float b) {
    __half2 t = __floats2half2_rn(a, b);
    return *(uint32_t*)&t;
}
__device__ __forceinline__ void split2h(float v0, float v1, uint32_t& hi, uint32_t& lo) {
    __half h0 = __float2half_rn(v0), h1 = __float2half_rn(v1);
    float r0 = v0 - __half2float(h0), r1 = v1 - __half2float(h1);
    __half2 H; H.x = h0; H.y = h1;
    hi = *(uint32_t*)&H;
    __half2 L = __floats2half2_rn(r0, r1);
    lo = *(uint32_t*)&L;
}

// ---------------- LayerNorm -> fp16 hi/lo ----------------
__global__ __launch_bounds__(256) void ln_kernel(
    const float* __restrict__ x, const float* __restrict__ gamma,
    const float* __restrict__ beta, __half* __restrict__ hi,
    __half* __restrict__ lo)
{
    int row = blockIdx.x;
    int tid = threadIdx.x;
    const float4* xr = (const float4*)(x + (size_t)row * D_MODEL);
    float4 v = xr[tid];
    float s  = v.x + v.y + v.z + v.w;
    float ss = v.x*v.x + v.y*v.y + v.z*v.z + v.w*v.w;
    #pragma unroll
    for (int o = 16; o; o >>= 1) {
        s  += __shfl_xor_sync(0xffffffffu, s,  o);
        ss += __shfl_xor_sync(0xffffffffu, ss, o);
    }
    __shared__ float rs[8], rss[8];
    int w = tid >> 5;
    if ((tid & 31) == 0) { rs[w] = s; rss[w] = ss; }
    __syncthreads();
    float S0 = 0.f, SS0 = 0.f;
    #pragma unroll
    for (int i = 0; i < 8; i++) { S0 += rs[i]; SS0 += rss[i]; }
    float mean = S0 * (1.0f / D_MODEL);
    float var  = SS0 * (1.0f / D_MODEL) - mean * mean;
    float rstd = rsqrtf(var + 1e-5f);
    float4 gg = ((const float4*)gamma)[tid];
    float4 bb = ((const float4*)beta)[tid];
    float o0 = (v.x - mean) * rstd * gg.x + bb.x;
    float o1 = (v.y - mean) * rstd * gg.y + bb.y;
    float o2 = (v.z - mean) * rstd * gg.z + bb.z;
    float o3 = (v.w - mean) * rstd * gg.w + bb.w;
    uint32_t h0, l0, h1, l1;
    split2h(o0, o1, h0, l0);
    split2h(o2, o3, h1, l1);
    size_t base = (size_t)row * D_MODEL + tid * 4;
    *(uint2*)&hi[base] = make_uint2(h0, h1);
    *(uint2*)&lo[base] = make_uint2(l0, l1);
}

// ---------------- weight transpose + fp16: w[K,N] fp32 -> [N,K] fp16 ----------------
__global__ __launch_bounds__(256) void split_w(
    const float* __restrict__ w, __half* __restrict__ out, int K, int N)
{
    __shared__ float tile[32][33];
    int n0 = blockIdx.x * 32, k0 = blockIdx.y * 32;
    int tx = threadIdx.x, ty = threadIdx.y;   // (32, 8)
    #pragma unroll
    for (int r = 0; r < 4; r++)
        tile[ty + 8 * r][tx] = w[(size_t)(k0 + ty + 8 * r) * N + n0 + tx];
    __syncthreads();
    #pragma unroll
    for (int r = 0; r < 4; r++) {
        float v = tile[tx][ty + 8 * r];
        size_t o = (size_t)(n0 + ty + 8 * r) * K + k0 + tx;
        out[o] = __float2half_rn(v);
    }
}

// ---------------- mask pack: 64 ints -> 1 uint64 bitmask ----------------
__global__ __launch_bounds__(256) void mask_pack(
    const int* __restrict__ m, unsigned long long* __restrict__ pk, int total)
{
    int idx = blockIdx.x * 256 + threadIdx.x;
    if (idx >= total) return;
    const int4* p = (const int4*)m + (size_t)idx * 16;
    unsigned long long w = 0;
    #pragma unroll
    for (int i = 0; i < 16; i++) {
        int4 v = p[i];
        w |= (unsigned long long)(v.x != 0) << (i * 4 + 0);
        w |= (unsigned long long)(v.y != 0) << (i * 4 + 1);
        w |= (unsigned long long)(v.z != 0) << (i * 4 + 2);
        w |= (unsigned long long)(v.w != 0) << (i * 4 + 3);
    }
    pk[idx] = w;
}

// ---------------- fp16 2-product GEMM ----------------
// C[M,N] = A[M,K] @ W[K,N] (W stored [N,K] fp16) + bias
// EPI: 1 bias+GELU -> hi/lo, 2 bias+residual -> fp32, 3 bias -> hi/lo, 5 bias -> hi only
__device__ __forceinline__ float gelu_exact(float x) {
    return 0.5f * x * (1.0f + erff(x * 0.70710678118654752f));
}

#define GM_AHI   0
#define GM_ALO   16384
#define GM_B     32768
#define GM_SSZ   49152
#define GM_SMEM  (2 * GM_SSZ)

template<int EPI>
__global__ __launch_bounds__(256) void gemm_mma(
    const __half* __restrict__ Ahi, const __half* __restrict__ Alo,
    const __half* __restrict__ B,
    const float* __restrict__ bias, const float* __restrict__ res,
    float* __restrict__ C, __half* __restrict__ Chi,
    __half* __restrict__ Clo, int M, int N, int K)
{
    extern __shared__ char smem[];
    uint32_t base = smem_u32(smem);
    int tid  = threadIdx.x;
    int lane = tid & 31;
    int wid  = tid >> 5;
    int warp_m = wid & 3;
    int warp_n = wid >> 2;
    int bm = blockIdx.y * 128, bn = blockIdx.x * 128;

    float acc[2][8][4];
    #pragma unroll
    for (int i = 0; i < 2; i++)
        #pragma unroll
        for (int j = 0; j < 8; j++)
            #pragma unroll
            for (int t = 0; t < 4; t++) acc[i][j][t] = 0.f;

    auto load_tile = [&](uint32_t sdst, const __half* g, int rowBase, int k0) {
        #pragma unroll
        for (int i = 0; i < 4; i++) {
            int f = i * 256 + tid;
            int row = f >> 3, c = f & 7;
            const __half* gp = g + (size_t)(rowBase + row) * K + k0 + c * 8;
            uint32_t off = row * 128 + c * 16;
            uint32_t sw = off ^ ((off >> 3) & 0x70);
            CP_ASYNC16(sdst + sw, gp);
        }
    };
    auto load_chunk = [&](int stage, int k0) {
        uint32_t sb = base + stage * GM_SSZ;
        load_tile(sb + GM_AHI, Ahi, bm, k0);
        load_tile(sb + GM_ALO, Alo, bm, k0);
        load_tile(sb + GM_B,   B,   bn, k0);
        CP_COMMIT();
    };

    int a_row = warp_m * 32 + (lane & 15);
    int a_kh  = lane >> 4;
    int b_row = warp_n * 64 + ((lane >> 4) & 1) * 8 + (lane & 7);
    int b_kh  = (lane >> 3) & 1;

    int nCh = K >> 6;
    load_chunk(0, 0);

    for (int it = 0; it < nCh; it++) {
        int buf = it & 1;
        if (it + 1 < nCh) { load_chunk(buf ^ 1, (it + 1) << 6); CP_WAIT(1); }
        else              { CP_WAIT(0); }
        __syncthreads();

        uint32_t sb = base + buf * GM_SSZ;
        #pragma unroll
        for (int ks = 0; ks < 4; ks++) {
            uint32_t ah[2][4], al[2][4];
            #pragma unroll
            for (int mf = 0; mf < 2; mf++) {
                int row = a_row + mf * 16;
                uint32_t col = (uint32_t)((ks * 2 + a_kh) ^ (row & 7)) * 16;
                uint32_t ad = sb + GM_AHI + row * 128 + col;
                LDSM_X4(ah[mf][0], ah[mf][1], ah[mf][2], ah[mf][3], ad);
                ad = sb + GM_ALO + row * 128 + col;
                LDSM_X4(al[mf][0], al[mf][1], al[mf][2], al[mf][3], ad);
            }
            #pragma unroll
            for (int nfp = 0; nfp < 4; nfp++) {
                int row = b_row + nfp * 16;
                uint32_t col = (uint32_t)((ks * 2 + b_kh) ^ (row & 7)) * 16;
                uint32_t bh[4];
                uint32_t bd = sb + GM_B + row * 128 + col;
                LDSM_X4(bh[0], bh[1], bh[2], bh[3], bd);
                #pragma unroll
                for (int mf = 0; mf < 2; mf++) {
                    #pragma unroll
                    for (int nn = 0; nn < 2; nn++) {
                        float* c = acc[mf][nfp * 2 + nn];
                        mma16816(c, ah[mf], &bh[nn * 2]);
                        mma16816(c, al[mf], &bh[nn * 2]);
                    }
                }
            }
        }
        __syncthreads();
    }

    int mrow0 = bm + warp_m * 32 + (lane >> 2);
    int ncol0 = bn + warp_n * 64 + (lane & 3) * 2;
    #pragma unroll
    for (int mf = 0; mf < 2; mf++) {
        #pragma unroll
        for (int nf = 0; nf < 8; nf++) {
            int n = ncol0 + nf * 8;
            float b0 = bias[n], b1 = bias[n + 1];
            #pragma unroll
            for (int half = 0; half < 2; half++) {
                int m = mrow0 + mf * 16 + half * 8;
                float v0 = acc[mf][nf][half * 2 + 0] + b0;
                float v1 = acc[mf][nf][half * 2 + 1] + b1;
                size_t o = (size_t)m * N + n;
                if (EPI == 1) { v0 = gelu_exact(v0); v1 = gelu_exact(v1); }
                if (EPI == 2) {
                    float2 rv = *(const float2*)&res[o];
                    v0 += rv.x; v1 += rv.y;
                    *(float2*)&C[o] = make_float2(v0, v1);
                } else if (EPI == 5) {
                    *(uint32_t*)&Chi[o] = pack_h(v0, v1);
                } else {
                    uint32_t hw, lw;
                    split2h(v0, v1, hw, lw);
                    *(uint32_t*)&Chi[o] = hw;
                    *(uint32_t*)&Clo[o] = lw;
                }
            }
        }
    }
}

// ---------------- flash attention on fp16 mma.sync ----------------
// grid (S/64, H, B), block 128. Scores: (qh+ql)*k = 2 mma; PV: 1 mma.
#define AT_QHI   0
#define AT_QLO   8192
#define AT_ST    16384
#define AT_KH    0
#define AT_V     8192
#define AT_BIAS  16384
#define AT_SSZ   16896
#define AT_SMEM  (AT_ST + 2 * AT_SSZ)

__global__ __launch_bounds__(128) void attn_mma(
    const __half* __restrict__ Qhi, const __half* __restrict__ Qlo,
    const __half* __restrict__ Khi, const __half* __restrict__ Vhi,
    const float* __restrict__ bt, const unsigned long long* __restrict__ mpk,
    __half* __restrict__ Ohi, __half* __restrict__ Olo)
{
    extern __shared__ char smem[];
    uint32_t base = smem_u32(smem);

    int b  = blockIdx.z, h = blockIdx.y;
    int q0 = blockIdx.x * 64;
    int tid  = threadIdx.x;
    int lane = tid & 31;
    int wid  = tid >> 5;
    size_t headoff = (size_t)h * HEAD_D;

    // ---- Q tile load (64 x 64, hi+lo) ----
    #pragma unroll
    for (int i = 0; i < 4; i++) {
        int f = i * 128 + tid;
        int row = f >> 3, c = f & 7;
        uint32_t sw = row * 128 + (uint32_t)((c ^ (row & 7)) * 16);
        const __half* gp = Qhi + ((size_t)(b * S_LEN + q0 + row)) * D_MODEL + headoff + c * 8;
        CP_ASYNC16(base + AT_QHI + sw, gp);
        gp = Qlo + ((size_t)(b * S_LEN + q0 + row)) * D_MODEL + headoff + c * 8;
        CP_ASYNC16(base + AT_QLO + sw, gp);
    }
    CP_COMMIT();

    auto load_kv = [&](int s, int kt) {
        uint32_t sb = base + AT_ST + s * AT_SSZ;
        int kr = kt * 64;
        #pragma unroll
        for (int i = 0; i < 4; i++) {
            int f = i * 128 + tid;
            int row = f >> 3, c = f & 7;
            uint32_t sw = row * 128 + (uint32_t)((c ^ (row & 7)) * 16);
            size_t gb = ((size_t)(b * S_LEN + kr + row)) * D_MODEL + headoff + c * 8;
            CP_ASYNC16(sb + AT_KH + sw, Khi + gb);
            CP_ASYNC16(sb + AT_V  + sw, Vhi + gb);
        }
        int d = kr - q0 + tid - 63 + MAXM1;
        CP_ASYNC4(sb + AT_BIAS + tid * 4, bt + (size_t)d * NUM_H + h);
        CP_COMMIT();
    };

    load_kv(0, 0);
    CP_WAIT(0);
    __syncthreads();

    // ---- hoist Q fragments ----
    int a_row = wid * 16 + (lane & 15);
    int a_kh  = lane >> 4;
    uint32_t qh[4][4], ql[4][4];
    #pragma unroll
    for (int ks = 0; ks < 4; ks++) {
        uint32_t col = (uint32_t)(((ks * 2 + a_kh) ^ (a_row & 7)) * 16);
        uint32_t ad = base + AT_QHI + a_row * 128 + col;
        LDSM_X4(qh[ks][0], qh[ks][1], qh[ks][2], qh[ks][3], ad);
        ad = base + AT_QLO + a_row * 128 + col;
        LDSM_X4(ql[ks][0], ql[ks][1], ql[ks][2], ql[ks][3], ad);
    }

    float ctx[8][4];
    #pragma unroll
    for (int i = 0; i < 8; i++)
        #pragma unroll
        for (int j = 0; j < 4; j++) ctx[i][j] = 0.f;
    float m0 = -3.0e38f, m1 = -3.0e38f, l0 = 0.f, l1 = 0.f;

    int r_loc0 = wid * 16 + (lane >> 2);
    int cbase  = (lane & 3) * 2;
    int b_row_base = ((lane >> 4) & 1) * 8 + (lane & 7);
    int b_kh = (lane >> 3) & 1;
    int v_i  = lane >> 3, v_j = lane & 7;

    const int nKT = S_LEN / 64;
    for (int kt = 0; kt < nKT; kt++) {
        int s = kt & 1;
        if (kt + 1 < nKT) { load_kv(s ^ 1, kt + 1); CP_WAIT(1); }
        else              { CP_WAIT(0); }
        __syncthreads();
        uint32_t sb = base + AT_ST + s * AT_SSZ;

        unsigned long long mw0 = mpk[((size_t)(b * S_LEN) + q0 + r_loc0) * nKT + kt];
        unsigned long long mw1 = mpk[((size_t)(b * S_LEN) + q0 + r_loc0 + 8) * nKT + kt];

        float sacc[8][4];
        #pragma unroll
        for (int i = 0; i < 8; i++)
            #pragma unroll
            for (int j = 0; j < 4; j++) sacc[i][j] = 0.f;

        #pragma unroll
        for (int ks = 0; ks < 4; ks++) {
            #pragma unroll
            for (int g = 0; g < 4; g++) {
                int row = g * 16 + b_row_base;
                uint32_t col = (uint32_t)(((ks * 2 + b_kh) ^ (row & 7)) * 16);
                uint32_t bh[4];
                uint32_t bd = sb + AT_KH + row * 128 + col;
                LDSM_X4(bh[0], bh[1], bh[2], bh[3], bd);
                mma16816(sacc[2*g],   qh[ks], &bh[0]);
                mma16816(sacc[2*g+1], qh[ks], &bh[2]);
                mma16816(sacc[2*g],   ql[ks], &bh[0]);
                mma16816(sacc[2*g+1], ql[ks], &bh[2]);
            }
        }

        const float* bs = (const float*)(smem + AT_ST + s * AT_SSZ + AT_BIAS);
        float mx0 = -3.0e38f, mx1 = -3.0e38f;
        #pragma unroll
        for (int f = 0; f < 8; f++) {
            int c0 = f * 8 + cbase;
            int i0 = c0 - r_loc0 + 63;
            float s00 = ((mw0 >> c0) & 1) ? sacc[f][0] * 0.125f + bs[i0]       : -1e9f;
            float s01 = ((mw0 >> (c0+1)) & 1) ? sacc[f][1] * 0.125f + bs[i0+1] : -1e9f;
            float s10 = ((mw1 >> c0) & 1) ? sacc[f][2] * 0.125f + bs[i0-8]     : -1e9f;
            float s11 = ((mw1 >> (c0+1)) & 1) ? sacc[f][3] * 0.125f + bs[i0-7] : -1e9f;
            sacc[f][0] = s00; sacc[f][1] = s01; sacc[f][2] = s10; sacc[f][3] = s11;
            mx0 = fmaxf(mx0, fmaxf(s00, s01));
            mx1 = fmaxf(mx1, fmaxf(s10, s11));
        }
        mx0 = fmaxf(mx0, __shfl_xor_sync(0xffffffffu, mx0, 1));
        mx0 = fmaxf(mx0, __shfl_xor_sync(0xffffffffu, mx0, 2));
        mx1 = fmaxf(mx1, __shfl_xor_sync(0xffffffffu, mx1, 1));
        mx1 = fmaxf(mx1, __shfl_xor_sync(0xffffffffu, mx1, 2));

        float mn0 = fmaxf(m0, mx0), mn1 = fmaxf(m1, mx1);
        float corr0 = __expf(m0 - mn0), corr1 = __expf(m1 - mn1);
        float rs0 = 0.f, rs1 = 0.f;
        #pragma unroll
        for (int f = 0; f < 8; f++) {
            float p00 = __expf(sacc[f][0] - mn0);
            float p01 = __expf(sacc[f][1] - mn0);
            float p10 = __expf(sacc[f][2] - mn1);
            float p11 = __expf(sacc[f][3] - mn1);
            sacc[f][0] = p00; sacc[f][1] = p01; sacc[f][2] = p10; sacc[f][3] = p11;
            rs0 += p00 + p01; rs1 += p10 + p11;
        }
        rs0 += __shfl_xor_sync(0xffffffffu, rs0, 1);
        rs0 += __shfl_xor_sync(0xffffffffu, rs0, 2);
        rs1 += __shfl_xor_sync(0xffffffffu, rs1, 1);
        rs1 += __shfl_xor_sync(0xffffffffu, rs1, 2);
        l0 = l0 * corr0 + rs0; m0 = mn0;
        l1 = l1 * corr1 + rs1; m1 = mn1;
        #pragma unroll
        for (int nf = 0; nf < 8; nf++) {
            ctx[nf][0] *= corr0; ctx[nf][1] *= corr0;
            ctx[nf][2] *= corr1; ctx[nf][3] *= corr1;
        }

        #pragma unroll
        for (int ks = 0; ks < 4; ks++) {
            uint32_t pf[4];
            pf[0] = pack_h(sacc[2*ks][0],   sacc[2*ks][1]);
            pf[1] = pack_h(sacc[2*ks][2],   sacc[2*ks][3]);
            pf[2] = pack_h(sacc[2*ks+1][0], sacc[2*ks+1][1]);
            pf[3] = pack_h(sacc[2*ks+1][2], sacc[2*ks+1][3]);
            #pragma unroll
            for (int vg = 0; vg < 4; vg++) {
                int row = ks * 16 + (v_i & 1) * 8 + v_j;
                uint32_t chunk = (uint32_t)(vg * 2 + (v_i >> 1));
                uint32_t vd = sb + AT_V + row * 128 + ((chunk ^ (row & 7)) * 16);
                uint32_t vb[4];
                LDSM_X4_T(vb[0], vb[1], vb[2], vb[3], vd);
                mma16816(ctx[2*vg],   pf, &vb[0]);
                mma16816(ctx[2*vg+1], pf, &vb[2]);
            }
        }
        __syncthreads();
    }

    float inv0 = 1.0f / l0, inv1 = 1.0f / l1;
    size_t tok0 = (size_t)(b * S_LEN + q0 + r_loc0);
    #pragma unroll
    for (int nf = 0; nf < 8; nf++) {
        int col = (int)headoff + nf * 8 + cbase;
        uint32_t hw, lw;
        split2h(ctx[nf][0] * inv0, ctx[nf][1] * inv0, hw, lw);
        *(uint32_t*)&Ohi[tok0 * D_MODEL + col] = hw;
        *(uint32_t*)&Olo[tok0 * D_MODEL + col] = lw;
        split2h(ctx[nf][2] * inv1, ctx[nf][3] * inv1, hw, lw);
        *(uint32_t*)&Ohi[(tok0 + 8) * D_MODEL + col] = hw;
        *(uint32_t*)&Olo[(tok0 + 8) * D_MODEL + col] = lw;
    }
}

// ---------------- host orchestration ----------------
extern "C" void kernel_launch(void* const* d_in, const int* in_sizes, int n_in,
                              void* d_out, int out_size)
{
    const float* x    = (const float*)d_in[0];
    const int*   mask = (const int*)  d_in[1];
    const float* wq = (const float*)d_in[2];
    const float* bq = (const float*)d_in[3];
    const float* wk = (const float*)d_in[4];
    const float* bk = (const float*)d_in[5];
    const float* wv = (const float*)d_in[6];
    const float* bv = (const float*)d_in[7];
    const float* wo = (const float*)d_in[8];
    const float* bo = (const float*)d_in[9];
    const float* w1 = (const float*)d_in[10];
    const float* b1 = (const float*)d_in[11];
    const float* w2 = (const float*)d_in[12];
    const float* b2 = (const float*)d_in[13];
    const float* g1  = (const float*)d_in[14];
    const float* be1 = (const float*)d_in[15];
    const float* g2  = (const float*)d_in[16];
    const float* be2 = (const float*)d_in[17];
    const float* bt  = (const float*)d_in[18];

    float* x1;
    __half *ahi, *alo, *qhi, *qlo, *khi, *vhi, *chi, *clo, *hhi, *hlo, *w;
    unsigned long long* mpk;
    cudaGetSymbolAddress((void**)&x1,  g_x1);
    cudaGetSymbolAddress((void**)&ahi, g_ahi);
    cudaGetSymbolAddress((void**)&alo, g_alo);
    cudaGetSymbolAddress((void**)&qhi, g_qhi);
    cudaGetSymbolAddress((void**)&qlo, g_qlo);
    cudaGetSymbolAddress((void**)&khi, g_khi);
    cudaGetSymbolAddress((void**)&vhi, g_vhi);
    cudaGetSymbolAddress((void**)&chi, g_chi);
    cudaGetSymbolAddress((void**)&clo, g_clo);
    cudaGetSymbolAddress((void**)&hhi, g_hhi);
    cudaGetSymbolAddress((void**)&hlo, g_hlo);
    cudaGetSymbolAddress((void**)&w,   g_w);
    cudaGetSymbolAddress((void**)&mpk, g_mpk);

    float* out = (float*)d_out;

    cudaFuncSetAttribute(gemm_mma<1>, cudaFuncAttributeMaxDynamicSharedMemorySize, GM_SMEM);
    cudaFuncSetAttribute(gemm_mma<2>, cudaFuncAttributeMaxDynamicSharedMemorySize, GM_SMEM);
    cudaFuncSetAttribute(gemm_mma<3>, cudaFuncAttributeMaxDynamicSharedMemorySize, GM_SMEM);
    cudaFuncSetAttribute(gemm_mma<5>, cudaFuncAttributeMaxDynamicSharedMemorySize, GM_SMEM);
    cudaFuncSetAttribute(attn_mma,    cudaFuncAttributeMaxDynamicSharedMemorySize, AT_SMEM);

    dim3 tb(32, 8);
    split_w<<<dim3(32, 32),  tb>>>(wq, w + 0 * MEG, 1024, 1024);
    split_w<<<dim3(32, 32),  tb>>>(wk, w + 1 * MEG, 1024, 1024);
    split_w<<<dim3(32, 32),  tb>>>(wv, w + 2 * MEG, 1024, 1024);
    split_w<<<dim3(32, 32),  tb>>>(wo, w + 3 * MEG, 1024, 1024);
    split_w<<<dim3(128, 32), tb>>>(w1, w + 4 * MEG, 1024, 4096);
    split_w<<<dim3(32, 128), tb>>>(w2, w + 8 * MEG, 4096, 1024);
    mask_pack<<<(B_SZ * S_LEN * (S_LEN / 64)) / 256, 256>>>(mask, mpk, B_SZ * S_LEN * (S_LEN / 64));

    // 1. pre-norm 1 -> hi/lo
    ln_kernel<<<N_TOK, 256>>>(x, g1, be1, ahi, alo);

    // 2. QKV projections
    dim3 gproj(D_MODEL / 128, N_TOK / 128);
    gemm_mma<3><<<gproj, 256, GM_SMEM>>>(ahi, alo, w + 0 * MEG, bq, nullptr, nullptr, qhi, qlo, N_TOK, D_MODEL, D_MODEL);
    gemm_mma<5><<<gproj, 256, GM_SMEM>>>(ahi, alo, w + 1 * MEG, bk, nullptr, nullptr, khi, nullptr, N_TOK, D_MODEL, D_MODEL);
    gemm_mma<5><<<gproj, 256, GM_SMEM>>>(ahi, alo, w + 2 * MEG, bv, nullptr, nullptr, vhi, nullptr, N_TOK, D_MODEL, D_MODEL);

    // 3. attention
    attn_mma<<<dim3(S_LEN / 64, NUM_H, B_SZ), 128, AT_SMEM>>>(qhi, qlo, khi, vhi, bt, mpk, chi, clo);

    // 4. output projection + residual(x) -> x1 fp32
    gemm_mma<2><<<gproj, 256, GM_SMEM>>>(chi, clo, w + 3 * MEG, bo, x, x1, nullptr, nullptr, N_TOK, D_MODEL, D_MODEL);

    // 5. pre-norm 2 -> hi/lo
    ln_kernel<<<N_TOK, 256>>>(x1, g2, be2, ahi, alo);

    // 6. FFN up + GELU -> h hi/lo
    gemm_mma<1><<<dim3(FF_DIM / 128, N_TOK / 128), 256, GM_SMEM>>>(ahi, alo, w + 4 * MEG, b1, nullptr, nullptr, hhi, hlo, N_TOK, FF_DIM, D_MODEL);

    // 7. FFN down + residual(x1) -> out
    gemm_mma<2><<<gproj, 256, GM_SMEM>>>(hhi, hlo, w + 8 * MEG, b2, x1, out, nullptr, nullptr, N_TOK, D_MODEL, FF_DIM);

    (void)in_sizes; (void)n_in; (void)out_size;
}

// round 8
// speedup vs baseline: 7.2419x; 1.5310x over previous
#include <cuda_runtime.h>
#include <cuda_fp16.h>
#include <math.h>
#include <stdint.h>

// ---------------- problem constants ----------------
#define B_SZ     2
#define S_LEN    2048
#define D_MODEL  1024
#define NUM_H    16
#define HEAD_D   64
#define FF_DIM   4096
#define N_TOK    (B_SZ * S_LEN)        // 4096
#define MAXM1    4999                  // MAX_SEQ_LEN - 1
#define MEG      (1024 * 1024)
#define QKV_N    3072

// ---------------- scratch (static device globals; no allocation) ----------------
__device__ float  g_x1 [N_TOK * D_MODEL];
__device__ float  g_bqkv[QKV_N];
__device__ __half g_a  [N_TOK * D_MODEL];        // LN output (fp16)
__device__ __half g_qkv[(size_t)N_TOK * QKV_N];  // interleaved q|k|v per token
__device__ __half g_c  [N_TOK * D_MODEL];        // attention ctx
__device__ __half g_h  [N_TOK * FF_DIM];         // FFN hidden
__device__ __half g_w  [12 * MEG];               // all weights [N,K] fp16
__device__ unsigned long long g_mpk[(size_t)B_SZ * S_LEN * (S_LEN / 64)];

// ---------------- PTX helpers (portable sm_80+ only) ----------------
__device__ __forceinline__ uint32_t smem_u32(const void* p) {
    uint32_t a;
    asm("{ .reg .u64 t; cvta.to.shared.u64 t, %1; cvt.u32.u64 %0, t; }" : "=r"(a) : "l"(p));
    return a;
}

#define CP_ASYNC16(saddr, gptr) \
    asm volatile("cp.async.cg.shared.global [%0], [%1], 16;" :: "r"(saddr), "l"(gptr))
#define CP_ASYNC4(saddr, gptr) \
    asm volatile("cp.async.ca.shared.global [%0], [%1], 4;" :: "r"(saddr), "l"(gptr))
#define CP_COMMIT() asm volatile("cp.async.commit_group;" ::: "memory")
#define CP_WAIT(n)  asm volatile("cp.async.wait_group %0;" :: "n"(n) : "memory")

#define LDSM_X4(r0, r1, r2, r3, addr) \
    asm volatile("ldmatrix.sync.aligned.m8n8.x4.shared.b16 {%0,%1,%2,%3}, [%4];" \
                 : "=r"(r0), "=r"(r1), "=r"(r2), "=r"(r3) : "r"(addr))
#define LDSM_X4_T(r0, r1, r2, r3, addr) \
    asm volatile("ldmatrix.sync.aligned.m8n8.x4.trans.shared.b16 {%0,%1,%2,%3}, [%4];" \
                 : "=r"(r0), "=r"(r1), "=r"(r2), "=r"(r3) : "r"(addr))

__device__ __forceinline__ void mma16816(float* c, const uint32_t* a, const uint32_t* b) {
    asm volatile("mma.sync.aligned.m16n8k16.row.col.f32.f16.f16.f32 "
        "{%0,%1,%2,%3}, {%4,%5,%6,%7}, {%8,%9}, {%0,%1,%2,%3};"
        : "+f"(c[0]), "+f"(c[1]), "+f"(c[2]), "+f"(c[3])
        : "r"(a[0]), "r"(a[1]), "r"(a[2]), "r"(a[3]), "r"(b[0]), "r"(b[1]));
}

__device__ __forceinline__ uint32_t pack_h(float a, float b) {
    __half2 t = __floats2half2_rn(a, b);
    return *(uint32_t*)&t;
}

// ---------------- LayerNorm -> fp16 ----------------
__global__ __launch_bounds__(256) void ln_kernel(
    const float* __restrict__ x, const float* __restrict__ gamma,
    const float* __restrict__ beta, __half* __restrict__ o)
{
    int row = blockIdx.x;
    int tid = threadIdx.x;
    const float4* xr = (const float4*)(x + (size_t)row * D_MODEL);
    float4 v = xr[tid];
    float s  = v.x + v.y + v.z + v.w;
    float ss = v.x*v.x + v.y*v.y + v.z*v.z + v.w*v.w;
    #pragma unroll
    for (int of = 16; of; of >>= 1) {
        s  += __shfl_xor_sync(0xffffffffu, s,  of);
        ss += __shfl_xor_sync(0xffffffffu, ss, of);
    }
    __shared__ float rs[8], rss[8];
    int w = tid >> 5;
    if ((tid & 31) == 0) { rs[w] = s; rss[w] = ss; }
    __syncthreads();
    float S0 = 0.f, SS0 = 0.f;
    #pragma unroll
    for (int i = 0; i < 8; i++) { S0 += rs[i]; SS0 += rss[i]; }
    float mean = S0 * (1.0f / D_MODEL);
    float var  = SS0 * (1.0f / D_MODEL) - mean * mean;
    float rstd = rsqrtf(var + 1e-5f);
    float4 gg = ((const float4*)gamma)[tid];
    float4 bb = ((const float4*)beta)[tid];
    float o0 = (v.x - mean) * rstd * gg.x + bb.x;
    float o1 = (v.y - mean) * rstd * gg.y + bb.y;
    float o2 = (v.z - mean) * rstd * gg.z + bb.z;
    float o3 = (v.w - mean) * rstd * gg.w + bb.w;
    size_t base = (size_t)row * D_MODEL + tid * 4;
    *(uint2*)&o[base] = make_uint2(pack_h(o0, o1), pack_h(o2, o3));
}

// ---------------- weight transpose + fp16: w[K,N] fp32 -> [N,K] fp16 ----------------
__global__ __launch_bounds__(256) void split_w(
    const float* __restrict__ w, __half* __restrict__ out, int K, int N)
{
    __shared__ float tile[32][33];
    int n0 = blockIdx.x * 32, k0 = blockIdx.y * 32;
    int tx = threadIdx.x, ty = threadIdx.y;   // (32, 8)
    #pragma unroll
    for (int r = 0; r < 4; r++)
        tile[ty + 8 * r][tx] = w[(size_t)(k0 + ty + 8 * r) * N + n0 + tx];
    __syncthreads();
    #pragma unroll
    for (int r = 0; r < 4; r++) {
        float v = tile[tx][ty + 8 * r];
        size_t o = (size_t)(n0 + ty + 8 * r) * K + k0 + tx;
        out[o] = __float2half_rn(v);
    }
}

// ---------------- bias concat for fused QKV ----------------
__global__ void concat_bias(const float* __restrict__ bq, const float* __restrict__ bk,
                            const float* __restrict__ bv, float* __restrict__ o)
{
    int i = blockIdx.x * 256 + threadIdx.x;
    if (i >= QKV_N) return;
    o[i] = i < 1024 ? bq[i] : (i < 2048 ? bk[i - 1024] : bv[i - 2048]);
}

// ---------------- mask pack: 64 ints -> 1 uint64 bitmask ----------------
__global__ __launch_bounds__(256) void mask_pack(
    const int* __restrict__ m, unsigned long long* __restrict__ pk, int total)
{
    int idx = blockIdx.x * 256 + threadIdx.x;
    if (idx >= total) return;
    const int4* p = (const int4*)m + (size_t)idx * 16;
    unsigned long long w = 0;
    #pragma unroll
    for (int i = 0; i < 16; i++) {
        int4 v = p[i];
        w |= (unsigned long long)(v.x != 0) << (i * 4 + 0);
        w |= (unsigned long long)(v.y != 0) << (i * 4 + 1);
        w |= (unsigned long long)(v.z != 0) << (i * 4 + 2);
        w |= (unsigned long long)(v.w != 0) << (i * 4 + 3);
    }
    pk[idx] = w;
}

// ---------------- fp16 GEMM: C[M,N] = A[M,K] @ W[K,N] (W stored [N,K]) + bias ----------------
// EPI: 1 bias+GELU -> fp16, 2 bias+residual -> fp32, 5 bias -> fp16
__device__ __forceinline__ float gelu_exact(float x) {
    return 0.5f * x * (1.0f + erff(x * 0.70710678118654752f));
}

#define GM_A     0
#define GM_B     16384
#define GM_SSZ   32768
#define GM_SMEM  (2 * GM_SSZ)

template<int EPI>
__global__ __launch_bounds__(256) void gemm_mma(
    const __half* __restrict__ A, const __half* __restrict__ B,
    const float* __restrict__ bias, const float* __restrict__ res,
    float* __restrict__ C, __half* __restrict__ Ch, int M, int N, int K)
{
    extern __shared__ char smem[];
    uint32_t base = smem_u32(smem);
    int tid  = threadIdx.x;
    int lane = tid & 31;
    int wid  = tid >> 5;
    int warp_m = wid & 3;
    int warp_n = wid >> 2;
    int bm = blockIdx.y * 128, bn = blockIdx.x * 128;

    float acc[2][8][4];
    #pragma unroll
    for (int i = 0; i < 2; i++)
        #pragma unroll
        for (int j = 0; j < 8; j++)
            #pragma unroll
            for (int t = 0; t < 4; t++) acc[i][j][t] = 0.f;

    auto load_tile = [&](uint32_t sdst, const __half* g, int rowBase, int k0) {
        #pragma unroll
        for (int i = 0; i < 4; i++) {
            int f = i * 256 + tid;
            int row = f >> 3, c = f & 7;
            const __half* gp = g + (size_t)(rowBase + row) * K + k0 + c * 8;
            uint32_t off = row * 128 + c * 16;
            uint32_t sw = off ^ ((off >> 3) & 0x70);
            CP_ASYNC16(sdst + sw, gp);
        }
    };
    auto load_chunk = [&](int stage, int k0) {
        uint32_t sb = base + stage * GM_SSZ;
        load_tile(sb + GM_A, A, bm, k0);
        load_tile(sb + GM_B, B, bn, k0);
        CP_COMMIT();
    };

    int a_row = warp_m * 32 + (lane & 15);
    int a_kh  = lane >> 4;
    int b_row = warp_n * 64 + ((lane >> 4) & 1) * 8 + (lane & 7);
    int b_kh  = (lane >> 3) & 1;

    int nCh = K >> 6;
    load_chunk(0, 0);

    for (int it = 0; it < nCh; it++) {
        int buf = it & 1;
        if (it + 1 < nCh) { load_chunk(buf ^ 1, (it + 1) << 6); CP_WAIT(1); }
        else              { CP_WAIT(0); }
        __syncthreads();

        uint32_t sb = base + buf * GM_SSZ;
        #pragma unroll
        for (int ks = 0; ks < 4; ks++) {
            uint32_t ah[2][4];
            #pragma unroll
            for (int mf = 0; mf < 2; mf++) {
                int row = a_row + mf * 16;
                uint32_t col = (uint32_t)((ks * 2 + a_kh) ^ (row & 7)) * 16;
                uint32_t ad = sb + GM_A + row * 128 + col;
                LDSM_X4(ah[mf][0], ah[mf][1], ah[mf][2], ah[mf][3], ad);
            }
            #pragma unroll
            for (int nfp = 0; nfp < 4; nfp++) {
                int row = b_row + nfp * 16;
                uint32_t col = (uint32_t)((ks * 2 + b_kh) ^ (row & 7)) * 16;
                uint32_t bh[4];
                uint32_t bd = sb + GM_B + row * 128 + col;
                LDSM_X4(bh[0], bh[1], bh[2], bh[3], bd);
                #pragma unroll
                for (int mf = 0; mf < 2; mf++) {
                    #pragma unroll
                    for (int nn = 0; nn < 2; nn++)
                        mma16816(acc[mf][nfp * 2 + nn], ah[mf], &bh[nn * 2]);
                }
            }
        }
        __syncthreads();
    }

    int mrow0 = bm + warp_m * 32 + (lane >> 2);
    int ncol0 = bn + warp_n * 64 + (lane & 3) * 2;
    #pragma unroll
    for (int mf = 0; mf < 2; mf++) {
        #pragma unroll
        for (int nf = 0; nf < 8; nf++) {
            int n = ncol0 + nf * 8;
            float b0 = bias[n], b1 = bias[n + 1];
            #pragma unroll
            for (int half = 0; half < 2; half++) {
                int m = mrow0 + mf * 16 + half * 8;
                float v0 = acc[mf][nf][half * 2 + 0] + b0;
                float v1 = acc[mf][nf][half * 2 + 1] + b1;
                size_t o = (size_t)m * N + n;
                if (EPI == 1) {
                    v0 = gelu_exact(v0); v1 = gelu_exact(v1);
                    *(uint32_t*)&Ch[o] = pack_h(v0, v1);
                } else if (EPI == 2) {
                    float2 rv = *(const float2*)&res[o];
                    *(float2*)&C[o] = make_float2(v0 + rv.x, v1 + rv.y);
                } else {
                    *(uint32_t*)&Ch[o] = pack_h(v0, v1);
                }
            }
        }
    }
}

// ---------------- flash attention (fp16 mma, interleaved qkv) ----------------
// grid (S/64, H, B), block 128. qkv rows stride QKV_N: Q @h*64, K @1024+h*64, V @2048+h*64
#define AT_Q     0
#define AT_ST    8192
#define AT_K     0
#define AT_V     8192
#define AT_BIAS  16384
#define AT_SSZ   16896
#define AT_SMEM  (AT_ST + 2 * AT_SSZ)

__global__ __launch_bounds__(128) void attn_mma(
    const __half* __restrict__ qkv, const float* __restrict__ bt,
    const unsigned long long* __restrict__ mpk, __half* __restrict__ Oh)
{
    extern __shared__ char smem[];
    uint32_t base = smem_u32(smem);

    int b  = blockIdx.z, h = blockIdx.y;
    int q0 = blockIdx.x * 64;
    int tid  = threadIdx.x;
    int lane = tid & 31;
    int wid  = tid >> 5;
    int headoff = h * HEAD_D;

    // ---- Q tile load (64 x 64) ----
    #pragma unroll
    for (int i = 0; i < 4; i++) {
        int f = i * 128 + tid;
        int row = f >> 3, c = f & 7;
        uint32_t sw = row * 128 + (uint32_t)((c ^ (row & 7)) * 16);
        const __half* gp = qkv + ((size_t)(b * S_LEN + q0 + row)) * QKV_N + headoff + c * 8;
        CP_ASYNC16(base + AT_Q + sw, gp);
    }
    CP_COMMIT();

    auto load_kv = [&](int s, int kt) {
        uint32_t sb = base + AT_ST + s * AT_SSZ;
        int kr = kt * 64;
        #pragma unroll
        for (int i = 0; i < 4; i++) {
            int f = i * 128 + tid;
            int row = f >> 3, c = f & 7;
            uint32_t sw = row * 128 + (uint32_t)((c ^ (row & 7)) * 16);
            size_t gb = ((size_t)(b * S_LEN + kr + row)) * QKV_N + c * 8;
            CP_ASYNC16(sb + AT_K + sw, qkv + gb + 1024 + headoff);
            CP_ASYNC16(sb + AT_V + sw, qkv + gb + 2048 + headoff);
        }
        int d = kr - q0 + tid - 63 + MAXM1;
        CP_ASYNC4(sb + AT_BIAS + tid * 4, bt + (size_t)d * NUM_H + h);
        CP_COMMIT();
    };

    load_kv(0, 0);
    CP_WAIT(0);
    __syncthreads();

    // ---- hoist Q fragments ----
    int a_row = wid * 16 + (lane & 15);
    int a_kh  = lane >> 4;
    uint32_t qh[4][4];
    #pragma unroll
    for (int ks = 0; ks < 4; ks++) {
        uint32_t col = (uint32_t)(((ks * 2 + a_kh) ^ (a_row & 7)) * 16);
        uint32_t ad = base + AT_Q + a_row * 128 + col;
        LDSM_X4(qh[ks][0], qh[ks][1], qh[ks][2], qh[ks][3], ad);
    }

    float ctx[8][4];
    #pragma unroll
    for (int i = 0; i < 8; i++)
        #pragma unroll
        for (int j = 0; j < 4; j++) ctx[i][j] = 0.f;
    float m0 = -3.0e38f, m1 = -3.0e38f, l0 = 0.f, l1 = 0.f;

    int r_loc0 = wid * 16 + (lane >> 2);
    int cbase  = (lane & 3) * 2;
    int b_row_base = ((lane >> 4) & 1) * 8 + (lane & 7);
    int b_kh = (lane >> 3) & 1;
    int v_i  = lane >> 3, v_j = lane & 7;

    const int nKT = S_LEN / 64;
    for (int kt = 0; kt < nKT; kt++) {
        int s = kt & 1;
        if (kt + 1 < nKT) { load_kv(s ^ 1, kt + 1); CP_WAIT(1); }
        else              { CP_WAIT(0); }
        __syncthreads();
        uint32_t sb = base + AT_ST + s * AT_SSZ;

        unsigned long long mw0 = mpk[((size_t)(b * S_LEN) + q0 + r_loc0) * nKT + kt];
        unsigned long long mw1 = mpk[((size_t)(b * S_LEN) + q0 + r_loc0 + 8) * nKT + kt];

        float sacc[8][4];
        #pragma unroll
        for (int i = 0; i < 8; i++)
            #pragma unroll
            for (int j = 0; j < 4; j++) sacc[i][j] = 0.f;

        #pragma unroll
        for (int ks = 0; ks < 4; ks++) {
            #pragma unroll
            for (int g = 0; g < 4; g++) {
                int row = g * 16 + b_row_base;
                uint32_t col = (uint32_t)(((ks * 2 + b_kh) ^ (row & 7)) * 16);
                uint32_t bh[4];
                uint32_t bd = sb + AT_K + row * 128 + col;
                LDSM_X4(bh[0], bh[1], bh[2], bh[3], bd);
                mma16816(sacc[2*g],   qh[ks], &bh[0]);
                mma16816(sacc[2*g+1], qh[ks], &bh[2]);
            }
        }

        const float* bs = (const float*)(smem + AT_ST + s * AT_SSZ + AT_BIAS);
        float mx0 = -3.0e38f, mx1 = -3.0e38f;
        #pragma unroll
        for (int f = 0; f < 8; f++) {
            int c0 = f * 8 + cbase;
            int i0 = c0 - r_loc0 + 63;
            float s00 = ((mw0 >> c0) & 1) ? sacc[f][0] * 0.125f + bs[i0]       : -1e9f;
            float s01 = ((mw0 >> (c0+1)) & 1) ? sacc[f][1] * 0.125f + bs[i0+1] : -1e9f;
            float s10 = ((mw1 >> c0) & 1) ? sacc[f][2] * 0.125f + bs[i0-8]     : -1e9f;
            float s11 = ((mw1 >> (c0+1)) & 1) ? sacc[f][3] * 0.125f + bs[i0-7] : -1e9f;
            sacc[f][0] = s00; sacc[f][1] = s01; sacc[f][2] = s10; sacc[f][3] = s11;
            mx0 = fmaxf(mx0, fmaxf(s00, s01));
            mx1 = fmaxf(mx1, fmaxf(s10, s11));
        }
        mx0 = fmaxf(mx0, __shfl_xor_sync(0xffffffffu, mx0, 1));
        mx0 = fmaxf(mx0, __shfl_xor_sync(0xffffffffu, mx0, 2));
        mx1 = fmaxf(mx1, __shfl_xor_sync(0xffffffffu, mx1, 1));
        mx1 = fmaxf(mx1, __shfl_xor_sync(0xffffffffu, mx1, 2));

        float mn0 = fmaxf(m0, mx0), mn1 = fmaxf(m1, mx1);
        float corr0 = __expf(m0 - mn0), corr1 = __expf(m1 - mn1);
        float rs0 = 0.f, rs1 = 0.f;
        #pragma unroll
        for (int f = 0; f < 8; f++) {
            float p00 = __expf(sacc[f][0] - mn0);
            float p01 = __expf(sacc[f][1] - mn0);
            float p10 = __expf(sacc[f][2] - mn1);
            float p11 = __expf(sacc[f][3] - mn1);
            sacc[f][0] = p00; sacc[f][1] = p01; sacc[f][2] = p10; sacc[f][3] = p11;
            rs0 += p00 + p01; rs1 += p10 + p11;
        }
        rs0 += __shfl_xor_sync(0xffffffffu, rs0, 1);
        rs0 += __shfl_xor_sync(0xffffffffu, rs0, 2);
        rs1 += __shfl_xor_sync(0xffffffffu, rs1, 1);
        rs1 += __shfl_xor_sync(0xffffffffu, rs1, 2);
        l0 = l0 * corr0 + rs0; m0 = mn0;
        l1 = l1 * corr1 + rs1; m1 = mn1;
        #pragma unroll
        for (int nf = 0; nf < 8; nf++) {
            ctx[nf][0] *= corr0; ctx[nf][1] *= corr0;
            ctx[nf][2] *= corr1; ctx[nf][3] *= corr1;
        }

        #pragma unroll
        for (int ks = 0; ks < 4; ks++) {
            uint32_t pf[4];
            pf[0] = pack_h(sacc[2*ks][0],   sacc[2*ks][1]);
            pf[1] = pack_h(sacc[2*ks][2],   sacc[2*ks][3]);
            pf[2] = pack_h(sacc[2*ks+1][0], sacc[2*ks+1][1]);
            pf[3] = pack_h(sacc[2*ks+1][2], sacc[2*ks+1][3]);
            #pragma unroll
            for (int vg = 0; vg < 4; vg++) {
                int row = ks * 16 + (v_i & 1) * 8 + v_j;
                uint32_t chunk = (uint32_t)(vg * 2 + (v_i >> 1));
                uint32_t vd = sb + AT_V + row * 128 + ((chunk ^ (row & 7)) * 16);
                uint32_t vb[4];
                LDSM_X4_T(vb[0], vb[1], vb[2], vb[3], vd);
                mma16816(ctx[2*vg],   pf, &vb[0]);
                mma16816(ctx[2*vg+1], pf, &vb[2]);
            }
        }
        __syncthreads();
    }

    float inv0 = 1.0f / l0, inv1 = 1.0f / l1;
    size_t tok0 = (size_t)(b * S_LEN + q0 + r_loc0);
    #pragma unroll
    for (int nf = 0; nf < 8; nf++) {
        int col = headoff + nf * 8 + cbase;
        *(uint32_t*)&Oh[tok0 * D_MODEL + col]       = pack_h(ctx[nf][0] * inv0, ctx[nf][1] * inv0);
        *(uint32_t*)&Oh[(tok0 + 8) * D_MODEL + col] = pack_h(ctx[nf][2] * inv1, ctx[nf][3] * inv1);
    }
}

// ---------------- host orchestration ----------------
extern "C" void kernel_launch(void* const* d_in, const int* in_sizes, int n_in,
                              void* d_out, int out_size)
{
    const float* x    = (const float*)d_in[0];
    const int*   mask = (const int*)  d_in[1];
    const float* wq = (const float*)d_in[2];
    const float* bq = (const float*)d_in[3];
    const float* wk = (const float*)d_in[4];
    const float* bk = (const float*)d_in[5];
    const float* wv = (const float*)d_in[6];
    const float* bv = (const float*)d_in[7];
    const float* wo = (const float*)d_in[8];
    const float* bo = (const float*)d_in[9];
    const float* w1 = (const float*)d_in[10];
    const float* b1 = (const float*)d_in[11];
    const float* w2 = (const float*)d_in[12];
    const float* b2 = (const float*)d_in[13];
    const float* g1  = (const float*)d_in[14];
    const float* be1 = (const float*)d_in[15];
    const float* g2  = (const float*)d_in[16];
    const float* be2 = (const float*)d_in[17];
    const float* bt  = (const float*)d_in[18];

    float *x1, *bqkv;
    __half *a, *qkv, *c, *hbuf, *w;
    unsigned long long* mpk;
    cudaGetSymbolAddress((void**)&x1,   g_x1);
    cudaGetSymbolAddress((void**)&bqkv, g_bqkv);
    cudaGetSymbolAddress((void**)&a,    g_a);
    cudaGetSymbolAddress((void**)&qkv,  g_qkv);
    cudaGetSymbolAddress((void**)&c,    g_c);
    cudaGetSymbolAddress((void**)&hbuf, g_h);
    cudaGetSymbolAddress((void**)&w,    g_w);
    cudaGetSymbolAddress((void**)&mpk,  g_mpk);

    float* out = (float*)d_out;

    cudaFuncSetAttribute(gemm_mma<1>, cudaFuncAttributeMaxDynamicSharedMemorySize, GM_SMEM);
    cudaFuncSetAttribute(gemm_mma<2>, cudaFuncAttributeMaxDynamicSharedMemorySize, GM_SMEM);
    cudaFuncSetAttribute(gemm_mma<5>, cudaFuncAttributeMaxDynamicSharedMemorySize, GM_SMEM);
    cudaFuncSetAttribute(attn_mma,    cudaFuncAttributeMaxDynamicSharedMemorySize, AT_SMEM);

    dim3 tb(32, 8);
    // fused QKV weight block: [3072, 1024] fp16 (wq rows 0-1023, wk 1024-2047, wv 2048-3071)
    split_w<<<dim3(32, 32),  tb>>>(wq, w + 0 * MEG, 1024, 1024);
    split_w<<<dim3(32, 32),  tb>>>(wk, w + 1 * MEG, 1024, 1024);
    split_w<<<dim3(32, 32),  tb>>>(wv, w + 2 * MEG, 1024, 1024);
    split_w<<<dim3(32, 32),  tb>>>(wo, w + 3 * MEG, 1024, 1024);
    split_w<<<dim3(128, 32), tb>>>(w1, w + 4 * MEG, 1024, 4096);
    split_w<<<dim3(32, 128), tb>>>(w2, w + 8 * MEG, 4096, 1024);
    concat_bias<<<(QKV_N + 255) / 256, 256>>>(bq, bk, bv, bqkv);
    mask_pack<<<(B_SZ * S_LEN * (S_LEN / 64)) / 256, 256>>>(mask, mpk, B_SZ * S_LEN * (S_LEN / 64));

    // 1. pre-norm 1 -> fp16
    ln_kernel<<<N_TOK, 256>>>(x, g1, be1, a);

    // 2. fused QKV projection -> interleaved [tok, 3072]
    gemm_mma<5><<<dim3(QKV_N / 128, N_TOK / 128), 256, GM_SMEM>>>(
        a, w, bqkv, nullptr, nullptr, qkv, N_TOK, QKV_N, D_MODEL);

    // 3. attention
    attn_mma<<<dim3(S_LEN / 64, NUM_H, B_SZ), 128, AT_SMEM>>>(qkv, bt, mpk, c);

    // 4. output projection + residual(x) -> x1 fp32
    dim3 gproj(D_MODEL / 128, N_TOK / 128);
    gemm_mma<2><<<gproj, 256, GM_SMEM>>>(c, w + 3 * MEG, bo, x, x1, nullptr, N_TOK, D_MODEL, D_MODEL);

    // 5. pre-norm 2 -> fp16
    ln_kernel<<<N_TOK, 256>>>(x1, g2, be2, a);

    // 6. FFN up + GELU -> fp16
    gemm_mma<1><<<dim3(FF_DIM / 128, N_TOK / 128), 256, GM_SMEM>>>(
        a, w + 4 * MEG, b1, nullptr, nullptr, hbuf, N_TOK, FF_DIM, D_MODEL);

    // 7. FFN down + residual(x1) -> out
    gemm_mma<2><<<gproj, 256, GM_SMEM>>>(hbuf, w + 8 * MEG, b2, x1, out, nullptr, N_TOK, D_MODEL, FF_DIM);

    (void)in_sizes; (void)n_in; (void)out_size;
}